// round 12
// baseline (speedup 1.0000x reference)
#include <cuda_runtime.h>
#include <math.h>
#include <stdint.h>

#define DM 512
#define NH 8
#define ED 64
#define NB 2
#define SL 2048
#define MT (NB*SL)          // 4096 rows
#define NBH (NB*NH)         // 16 sequences
#define CK 128              // chunk length
#define NCH (SL/CK)         // 16 chunks

// ---------------- scratch (static device globals; no runtime alloc) --------
__device__ float g_q[MT*DM];
__device__ float g_k[MT*DM];
__device__ float g_v[MT*DM];
__device__ float g_attn[MT*DM];
__device__ float g_y[MT*DM];
__device__ float g_WqkvT[3*DM*DM];   // [1536][512], tf32-rounded
__device__ float g_WoutT[DM*DM];     // [512][512],  tf32-rounded
__device__ float g_Sloc[NBH*NCH*ED*ED];
__device__ float g_Sin [NBH*NCH*ED*ED];   // row-major carry-in states [e][f]
__device__ float g_zloc[NBH*NCH*ED];
__device__ float g_zin [NBH*NCH*ED];

__device__ __forceinline__ float lam_of(const float* dl, int h){
    return 0.99f + 0.01f/(1.0f + expf(-dl[h]));
}
__device__ __forceinline__ uint32_t f2tf32(float x){
    uint32_t r; asm("cvt.rna.tf32.f32 %0, %1;" : "=r"(r) : "f"(x)); return r;
}
__device__ __forceinline__ float round_tf32(float x){
    return __uint_as_float(f2tf32(x));
}
__device__ __forceinline__ void mma_tf32(float* c, const uint4& a, const uint2& b){
    asm volatile("mma.sync.aligned.m16n8k8.row.col.f32.tf32.tf32.f32 "
        "{%0,%1,%2,%3}, {%4,%5,%6,%7}, {%8,%9}, {%0,%1,%2,%3};"
        : "+f"(c[0]), "+f"(c[1]), "+f"(c[2]), "+f"(c[3])
        : "r"(a.x), "r"(a.y), "r"(a.z), "r"(a.w), "r"(b.x), "r"(b.y));
}
// fragment-pack index helpers (m16n8k8 tf32)
__device__ __forceinline__ int Aidx(int KS, int r, int k){
    return (((r>>4)*KS + (k>>3))*32 + (r&7)*4 + (k&3))*4 + ((r>>3)&1) + 2*((k>>2)&1);
}
__device__ __forceinline__ int Bidx(int KS, int n, int k){
    return (((n>>3)*KS + (k>>3))*32 + (n&7)*4 + (k&3))*2 + ((k>>2)&1);
}

// ------- fused W transpose + tf32 pre-round: Wt[n][k] = round(W[k][n]) ------
__global__ void transpose_kernel(const float* __restrict__ Wq,
                                 const float* __restrict__ Wo)
{
    __shared__ float tile[32][33];
    int bx = blockIdx.x;
    const float* W; float* Wt; int N;
    if (bx < 48){ W = Wq; Wt = g_WqkvT; N = 3*DM; }
    else        { bx -= 48; W = Wo; Wt = g_WoutT; N = DM; }
    const int n0 = bx*32, k0 = blockIdx.y*32;
    const int tx = threadIdx.x, ty = threadIdx.y;   // 32 x 8
    #pragma unroll
    for (int j=0;j<32;j+=8)
        tile[ty+j][tx] = W[(size_t)(k0+ty+j)*N + n0+tx];
    __syncthreads();
    #pragma unroll
    for (int j=0;j<32;j+=8)
        Wt[(size_t)(n0+ty+j)*DM + k0+tx] = round_tf32(tile[tx][ty+j]);
}

// =================== tf32 mma.sync GEMM: D = A @ Wt^T + b ===================
// __launch_bounds__(256,2): cap regs at 128 so 2 CTAs/SM fit (occupancy fix)
template<int MODE>
__global__ __launch_bounds__(256,2) void mma_gemm_kernel(const float* __restrict__ Ain,
                                                         const float* __restrict__ bias)
{
    extern __shared__ uint32_t sm[];        // 2 bufs x (A 4096 + B 4096) u32
    const float* A  = (MODE==0) ? Ain : g_attn;
    const float* Wt = (MODE==0) ? g_WqkvT : g_WoutT;
    const int m0 = blockIdx.y*128, n0 = blockIdx.x*128;
    const int t = threadIdx.x, lane = t&31, wid = t>>5;
    const int wm = wid&1, wn = wid>>1;

    const int c4    = (t&7)<<2;
    const int kkL   = c4>>3;
    const int cregL = (c4>>2)&1;
    const int rlo   = t>>3;
    const int lane0 = (rlo&7)<<2;
    const int rhi   = (t>>6)&1;
    const int mt0   = t>>7;
    const int nt0   = (t>>6)&3;
    const int regA  = rhi + 2*cregL;

    float4 ra[4], rb[4];
    float acc[4][4][4];
    #pragma unroll
    for (int i=0;i<4;i++)
        #pragma unroll
        for (int j=0;j<4;j++)
            #pragma unroll
            for (int r=0;r<4;r++) acc[i][j][r]=0.f;

    auto ldg = [&](int c){
        const int k0 = c*32;
        #pragma unroll
        for (int i=0;i<4;i++){
            ra[i] = *(const float4*)&A [(size_t)(m0 + rlo + 32*i)*DM + k0 + c4];
            rb[i] = *(const float4*)&Wt[(size_t)(n0 + rlo + 32*i)*DM + k0 + c4];
        }
    };
    auto cvtA = [&](float x)->uint32_t {
        return (MODE==0) ? f2tf32(x) : __float_as_uint(x);
    };
    auto sts = [&](int buf){
        uint32_t* Ab = sm + buf*8192;
        uint32_t* Bb = Ab + 4096;
        #pragma unroll
        for (int i=0;i<4;i++){
            const int mt = mt0 + 2*i;
            const uint32_t ab = (uint32_t)(((mt*4 + kkL)*32 + lane0)*4 + regA);
            Ab[ab + 0*4] = cvtA(ra[i].x);
            Ab[ab + 1*4] = cvtA(ra[i].y);
            Ab[ab + 2*4] = cvtA(ra[i].z);
            Ab[ab + 3*4] = cvtA(ra[i].w);
            const int nt = nt0 + 4*i;
            const uint32_t bb = (uint32_t)(((nt*4 + kkL)*32 + lane0)*2 + cregL);
            Bb[bb + 0*2] = __float_as_uint(rb[i].x);
            Bb[bb + 1*2] = __float_as_uint(rb[i].y);
            Bb[bb + 2*2] = __float_as_uint(rb[i].z);
            Bb[bb + 3*2] = __float_as_uint(rb[i].w);
        }
    };
    auto compute = [&](int buf){
        const uint32_t* Ab = sm + buf*8192;
        const uint32_t* Bb = Ab + 4096;
        #pragma unroll
        for (int kk=0;kk<4;kk++){
            uint4 a[4]; uint2 b[4];
            #pragma unroll
            for (int i=0;i<4;i++)
                a[i] = *(const uint4*)&Ab[(((wm*4+i)*4+kk)*32 + lane)*4];
            #pragma unroll
            for (int j=0;j<4;j++)
                b[j] = *(const uint2*)&Bb[(((wn*4+j)*4+kk)*32 + lane)*2];
            #pragma unroll
            for (int i=0;i<4;i++)
                #pragma unroll
                for (int j=0;j<4;j++)
                    mma_tf32(acc[i][j], a[i], b[j]);
        }
    };

    ldg(0); sts(0); __syncthreads();
    #pragma unroll 1
    for (int c=0;c<16;c++){
        if (c<15) ldg(c+1);
        compute(c&1);
        if (c<15) sts((c+1)&1);
        __syncthreads();
    }

    int regi = 0; float* dst;
    if (MODE==0){
        regi = n0 >> 9;
        dst = (regi==0) ? g_q : (regi==1) ? g_k : g_v;
    } else dst = g_y;
    const int nsub = (MODE==0) ? (n0 - regi*512) : n0;
    const int rowl = lane>>2, colp = (lane&3)*2;

    #pragma unroll
    for (int i=0;i<4;i++){
        #pragma unroll
        for (int j=0;j<4;j++){
            const int nn = n0   + wn*32 + j*8 + colp;
            const int nc = nsub + wn*32 + j*8 + colp;
            const float b0v = __ldg(&bias[nn]);
            const float b1v = __ldg(&bias[nn+1]);
            float v[4] = { acc[i][j][0] + b0v, acc[i][j][1] + b1v,
                           acc[i][j][2] + b0v, acc[i][j][3] + b1v };
            if (MODE==0){
                if (regi==0){
                    #pragma unroll
                    for (int e=0;e<4;e++){ float x=(v[e]>0.f)?v[e]+1.f:expf(v[e]); v[e]=round_tf32(x*0.125f); }
                } else if (regi==1){
                    #pragma unroll
                    for (int e=0;e<4;e++){ float x=(v[e]>0.f)?v[e]+1.f:expf(v[e]); v[e]=round_tf32(x); }
                } else {
                    #pragma unroll
                    for (int e=0;e<4;e++) v[e]=round_tf32(v[e]);
                }
            }
            const int r0 = m0 + wm*64 + i*16 + rowl;
            *(float2*)&dst[(size_t)r0*DM + nc]     = make_float2(v[0], v[1]);
            *(float2*)&dst[(size_t)(r0+8)*DM + nc] = make_float2(v[2], v[3]);
        }
    }
}

// ============== chunk_local via mma: S_loc = (pw*K)^T @ V,  64x64x128 =======
__global__ __launch_bounds__(256) void chunk_local_kernel(const float* __restrict__ dl)
{
    extern __shared__ uint32_t sl[];
    uint32_t* Aa = sl;            // A-pack 64x128 (KS=16) : 8192 u32
    uint32_t* Bb = sl + 8192;     // B-pack 64x128 (KS=16) : 8192 u32
    __shared__ float pw[128];
    __shared__ float zpart[4][64];

    const int c = blockIdx.x, bh = blockIdx.y;
    const int b = bh / NH, h = bh % NH;
    const int t = threadIdx.x, lane = t&31, wid = t>>5;
    const int wm = wid&1, wn = wid>>1;
    const int g = lane>>2, tg = lane&3;
    const float lam = lam_of(dl, h);
    if (t < 128) pw[t] = exp2f((float)t * log2f(lam));
    __syncthreads();

    const size_t rowbase = ((size_t)b*SL + (size_t)c*CK)*DM + h*ED;
    for (int vi = t; vi < 2048; vi += 256){
        const int j = vi >> 4, e4 = (vi & 15)*4;
        const float w = pw[127-j];
        float4 kv = *(const float4*)&g_k[rowbase + (size_t)j*DM + e4];
        Aa[Aidx(16, e4+0, j)] = f2tf32(w*kv.x);
        Aa[Aidx(16, e4+1, j)] = f2tf32(w*kv.y);
        Aa[Aidx(16, e4+2, j)] = f2tf32(w*kv.z);
        Aa[Aidx(16, e4+3, j)] = f2tf32(w*kv.w);
        float4 vv = *(const float4*)&g_v[rowbase + (size_t)j*DM + e4];
        Bb[Bidx(16, e4+0, j)] = __float_as_uint(vv.x);
        Bb[Bidx(16, e4+1, j)] = __float_as_uint(vv.y);
        Bb[Bidx(16, e4+2, j)] = __float_as_uint(vv.z);
        Bb[Bidx(16, e4+3, j)] = __float_as_uint(vv.w);
    }
    {
        const int e = t & 63, part = t >> 6;
        float z = 0.f;
        #pragma unroll 4
        for (int j = part*32; j < part*32+32; j++)
            z += pw[127-j] * g_k[rowbase + (size_t)j*DM + e];
        zpart[part][e] = z;
    }
    __syncthreads();
    if (t < ED)
        g_zloc[((size_t)bh*NCH + c)*ED + t] =
            zpart[0][t] + zpart[1][t] + zpart[2][t] + zpart[3][t];

    float acc[2][2][4];
    #pragma unroll
    for (int i=0;i<2;i++)
        #pragma unroll
        for (int j=0;j<2;j++)
            #pragma unroll
            for (int r=0;r<4;r++) acc[i][j][r]=0.f;
    #pragma unroll
    for (int kk=0;kk<16;kk++){
        uint4 a[2]; uint2 b2[2];
        #pragma unroll
        for (int i=0;i<2;i++)
            a[i] = *(const uint4*)&Aa[(((wm*2+i)*16+kk)*32 + lane)*4];
        #pragma unroll
        for (int j=0;j<2;j++)
            b2[j] = *(const uint2*)&Bb[(((wn*2+j)*16+kk)*32 + lane)*2];
        #pragma unroll
        for (int i=0;i<2;i++)
            #pragma unroll
            for (int j=0;j<2;j++)
                mma_tf32(acc[i][j], a[i], b2[j]);
    }
    const size_t sb = ((size_t)bh*NCH + c)*ED*ED;
    #pragma unroll
    for (int i=0;i<2;i++){
        #pragma unroll
        for (int j=0;j<2;j++){
            const int e0 = wm*32 + i*16 + g;
            const int f0 = wn*16 + j*8 + tg*2;
            *(float2*)&g_Sloc[sb + e0*ED + f0]     = make_float2(acc[i][j][0], acc[i][j][1]);
            *(float2*)&g_Sloc[sb + (e0+8)*ED + f0] = make_float2(acc[i][j][2], acc[i][j][3]);
        }
    }
}

// ----- PARALLEL inter-chunk scan: one thread per state element -------------
__global__ __launch_bounds__(256) void scan_kernel(const float* __restrict__ dl)
{
    const int bh  = blockIdx.x;
    const int el  = blockIdx.y*256 + threadIdx.x;    // 0..4095
    const int h   = bh % NH;
    const float lam  = lam_of(dl, h);
    const float lamC = exp2f((float)CK * log2f(lam));
    const size_t base = (size_t)bh*NCH*ED*ED + el;

    float v[NCH];
    #pragma unroll
    for (int c=0;c<NCH;c++) v[c] = g_Sloc[base + (size_t)c*ED*ED];
    float s = 0.f;
    #pragma unroll
    for (int c=0;c<NCH;c++){
        g_Sin[base + (size_t)c*ED*ED] = s;
        s = lamC*s + v[c];
    }

    if (blockIdx.y == 0 && threadIdx.x < ED){
        const size_t zb = (size_t)bh*NCH*ED + threadIdx.x;
        float zv[NCH];
        #pragma unroll
        for (int c=0;c<NCH;c++) zv[c] = g_zloc[zb + (size_t)c*ED];
        float z = 0.f;
        #pragma unroll
        for (int c=0;c<NCH;c++){
            g_zin[zb + (size_t)c*ED] = z;
            z = lamC*z + zv[c];
        }
    }
}

// ================= chunk_out: P stays in registers =========================
__global__ __launch_bounds__(256,2) void chunk_out_kernel(const float* __restrict__ dl)
{
    extern __shared__ uint32_t su[];
    uint32_t* Kb = su;            // B-pack K: n=row j (128), k=e (64), KS=8 : 8192
    uint32_t* Vb = su + 8192;     // B-pack V^T: n=f (64), k=j (128), KS=16 : 8192
    uint32_t* Sb = su + 16384;    // B-pack S^T: n=f (64), k=e (64),  KS=8  : 4096
    __shared__ float pw[132];
    __shared__ float zs[64];

    const int c = blockIdx.x, bh = blockIdx.y;
    const int b = bh / NH, h = bh % NH;
    const int t = threadIdx.x, lane = t&31, wid = t>>5;
    const int g = lane>>2, tg = lane&3;
    const float lam = lam_of(dl, h);
    if (t <= 128) pw[t] = exp2f((float)t * log2f(lam));
    if (t < ED)   zs[t] = g_zin[((size_t)bh*NCH+c)*ED + t];

    const size_t rowbase = ((size_t)b*SL + (size_t)c*CK)*DM + h*ED;
    for (int idx = t; idx < 8192; idx += 256){
        const int r = idx >> 6, k = idx & 63;
        Kb[Bidx(8, r, k)]  = __float_as_uint(g_k[rowbase + (size_t)r*DM + k]);
        Vb[Bidx(16, k, r)] = __float_as_uint(g_v[rowbase + (size_t)r*DM + k]);
    }
    {
        const size_t sbase = ((size_t)bh*NCH + c)*ED*ED;
        for (int idx = t; idx < 4096; idx += 256){
            const int e = idx >> 6, f = idx & 63;
            Sb[Bidx(8, f, e)] = f2tf32(g_Sin[sbase + idx]);
        }
    }
    __syncthreads();

    const int rb    = wid*16;
    const int ii_lo = rb + g, ii_hi = ii_lo + 8;

    uint4 qf[8];
    #pragma unroll
    for (int kk=0;kk<8;kk++){
        const float* q0 = &g_q[rowbase + (size_t)ii_lo*DM + kk*8];
        const float* q1 = &g_q[rowbase + (size_t)ii_hi*DM + kk*8];
        qf[kk].x = __float_as_uint(q0[tg]);
        qf[kk].y = __float_as_uint(q1[tg]);
        qf[kk].z = __float_as_uint(q0[tg+4]);
        qf[kk].w = __float_as_uint(q1[tg+4]);
    }

    float dq_lo = 0.f, dq_hi = 0.f;
    #pragma unroll
    for (int kk=0;kk<8;kk++){
        dq_lo += __uint_as_float(qf[kk].x)*zs[kk*8+tg]
               + __uint_as_float(qf[kk].z)*zs[kk*8+tg+4];
        dq_hi += __uint_as_float(qf[kk].y)*zs[kk*8+tg]
               + __uint_as_float(qf[kk].w)*zs[kk*8+tg+4];
    }
    dq_lo += __shfl_xor_sync(0xffffffffu, dq_lo, 1);
    dq_lo += __shfl_xor_sync(0xffffffffu, dq_lo, 2);
    dq_hi += __shfl_xor_sync(0xffffffffu, dq_hi, 1);
    dq_hi += __shfl_xor_sync(0xffffffffu, dq_hi, 2);

    float acc1[8][4];
    #pragma unroll
    for (int j=0;j<8;j++)
        #pragma unroll
        for (int r=0;r<4;r++) acc1[j][r]=0.f;
    #pragma unroll
    for (int kk=0;kk<8;kk++){
        #pragma unroll
        for (int j=0;j<8;j++){
            uint2 bb = *(const uint2*)&Sb[((j*8+kk)*32 + lane)*2];
            mma_tf32(acc1[j], qf[kk], bb);
        }
    }

    uint4 accPq[16];
    #pragma unroll
    for (int j=0;j<16;j++) accPq[j] = make_uint4(0,0,0,0);
    #pragma unroll
    for (int kk=0;kk<8;kk++){
        #pragma unroll
        for (int j=0;j<16;j++){
            uint2 bb = *(const uint2*)&Kb[((j*8+kk)*32 + lane)*2];
            mma_tf32((float*)&accPq[j], qf[kk], bb);
        }
    }

    float dens_lo = 0.f, dens_hi = 0.f;
    #pragma unroll
    for (int j=0;j<16;j++){
        const int jj0 = j*8 + 2*tg;
        const float w00 = (jj0   <= ii_lo) ? pw[ii_lo-jj0]   : 0.f;
        const float w01 = (jj0+1 <= ii_lo) ? pw[ii_lo-jj0-1] : 0.f;
        const float w10 = (jj0   <= ii_hi) ? pw[ii_hi-jj0]   : 0.f;
        const float w11 = (jj0+1 <= ii_hi) ? pw[ii_hi-jj0-1] : 0.f;
        float c0 = w00*__uint_as_float(accPq[j].x);
        float c1 = w01*__uint_as_float(accPq[j].y);
        float c2 = w10*__uint_as_float(accPq[j].z);
        float c3 = w11*__uint_as_float(accPq[j].w);
        accPq[j].x = __float_as_uint(c0);
        accPq[j].y = __float_as_uint(c1);
        accPq[j].z = __float_as_uint(c2);
        accPq[j].w = __float_as_uint(c3);
        dens_lo += c0 + c1;
        dens_hi += c2 + c3;
    }
    dens_lo += __shfl_xor_sync(0xffffffffu, dens_lo, 1);
    dens_lo += __shfl_xor_sync(0xffffffffu, dens_lo, 2);
    dens_hi += __shfl_xor_sync(0xffffffffu, dens_hi, 1);
    dens_hi += __shfl_xor_sync(0xffffffffu, dens_hi, 2);

    const int srcA = (lane & 28) | (tg>>1);
    const int srcB = srcA + 2;
    const bool odd = (tg & 1);
    #pragma unroll
    for (int j=0;j<16;j++){
        float c0 = __uint_as_float(accPq[j].x);
        float c1 = __uint_as_float(accPq[j].y);
        float c2 = __uint_as_float(accPq[j].z);
        float c3 = __uint_as_float(accPq[j].w);
        float v0a = __shfl_sync(0xffffffffu, c0, srcA);
        float v1a = __shfl_sync(0xffffffffu, c1, srcA);
        float v2a = __shfl_sync(0xffffffffu, c2, srcA);
        float v3a = __shfl_sync(0xffffffffu, c3, srcA);
        float v0b = __shfl_sync(0xffffffffu, c0, srcB);
        float v1b = __shfl_sync(0xffffffffu, c1, srcB);
        float v2b = __shfl_sync(0xffffffffu, c2, srcB);
        float v3b = __shfl_sync(0xffffffffu, c3, srcB);
        accPq[j].x = f2tf32(odd ? v1a : v0a);
        accPq[j].y = f2tf32(odd ? v3a : v2a);
        accPq[j].z = f2tf32(odd ? v1b : v0b);
        accPq[j].w = f2tf32(odd ? v3b : v2b);
    }

    float acc2[8][4];
    #pragma unroll
    for (int j=0;j<8;j++)
        #pragma unroll
        for (int r=0;r<4;r++) acc2[j][r]=0.f;
    #pragma unroll
    for (int kk=0;kk<16;kk++){
        #pragma unroll
        for (int j=0;j<8;j++){
            uint2 bb = *(const uint2*)&Vb[((j*16+kk)*32 + lane)*2];
            mma_tf32(acc2[j], accPq[kk], bb);
        }
    }

    const int mrow = b*SL + c*CK;
    const float pw_lo = pw[ii_lo+1], pw_hi = pw[ii_hi+1];
    const float inv_lo = 1.f / (pw_lo*dq_lo + dens_lo + 1e-6f);
    const float inv_hi = 1.f / (pw_hi*dq_hi + dens_hi + 1e-6f);
    #pragma unroll
    for (int j=0;j<8;j++){
        const int f0 = j*8 + 2*tg;
        const float v0 = round_tf32((pw_lo*acc1[j][0] + acc2[j][0])*inv_lo);
        const float v1 = round_tf32((pw_lo*acc1[j][1] + acc2[j][1])*inv_lo);
        const float v2 = round_tf32((pw_hi*acc1[j][2] + acc2[j][2])*inv_hi);
        const float v3 = round_tf32((pw_hi*acc1[j][3] + acc2[j][3])*inv_hi);
        *(float2*)&g_attn[(size_t)(mrow+ii_lo)*DM + h*ED + f0] = make_float2(v0, v1);
        *(float2*)&g_attn[(size_t)(mrow+ii_hi)*DM + h*ED + f0] = make_float2(v2, v3);
    }
}

// ---------------- LayerNorm ------------------------------------------------
__global__ __launch_bounds__(128) void ln_kernel(const float* __restrict__ gg,
                                                 const float* __restrict__ bb,
                                                 float* __restrict__ out)
{
    const int row = blockIdx.x, t = threadIdx.x;
    __shared__ float red[8];
    float4 v = *(const float4*)&g_y[(size_t)row*DM + t*4];
    float s  = v.x+v.y+v.z+v.w;
    float s2 = v.x*v.x+v.y*v.y+v.z*v.z+v.w*v.w;
    #pragma unroll
    for (int o=16;o;o>>=1){
        s  += __shfl_xor_sync(0xffffffffu, s,  o);
        s2 += __shfl_xor_sync(0xffffffffu, s2, o);
    }
    const int w = t>>5;
    if ((t&31)==0){ red[w]=s; red[4+w]=s2; }
    __syncthreads();
    s  = red[0]+red[1]+red[2]+red[3];
    s2 = red[4]+red[5]+red[6]+red[7];
    const float mean = s*(1.0f/DM);
    const float var  = s2*(1.0f/DM) - mean*mean;
    const float inv  = rsqrtf(var + 1e-5f);
    float4 gv = *(const float4*)&gg[t*4];
    float4 bv = *(const float4*)&bb[t*4];
    float4 o;
    o.x = (v.x-mean)*inv*gv.x + bv.x;
    o.y = (v.y-mean)*inv*gv.y + bv.y;
    o.z = (v.z-mean)*inv*gv.z + bv.z;
    o.w = (v.w-mean)*inv*gv.w + bv.w;
    *(float4*)&out[(size_t)row*DM + t*4] = o;
}

// ---------------- launch ----------------------------------------------------
extern "C" void kernel_launch(void* const* d_in, const int* in_sizes, int n_in,
                              void* d_out, int out_size)
{
    const float* x     = (const float*)d_in[0];
    const float* W_qkv = (const float*)d_in[1];
    const float* b_qkv = (const float*)d_in[2];
    const float* W_out = (const float*)d_in[3];
    const float* b_out = (const float*)d_in[4];
    const float* dl    = (const float*)d_in[5];
    const float* ln_g  = (const float*)d_in[6];
    const float* ln_b  = (const float*)d_in[7];
    float* out = (float*)d_out;

    const int smem_cl = 16384*4;                                  // 65536 B
    const int smem_co = 20480*4;                                  // 81920 B
    const int smem_mm = 2*8192*4;                                 // 65536 B
    cudaFuncSetAttribute(chunk_local_kernel,
                         cudaFuncAttributeMaxDynamicSharedMemorySize, smem_cl);
    cudaFuncSetAttribute(chunk_out_kernel,
                         cudaFuncAttributeMaxDynamicSharedMemorySize, smem_co);
    cudaFuncSetAttribute(mma_gemm_kernel<0>,
                         cudaFuncAttributeMaxDynamicSharedMemorySize, smem_mm);
    cudaFuncSetAttribute(mma_gemm_kernel<1>,
                         cudaFuncAttributeMaxDynamicSharedMemorySize, smem_mm);

    transpose_kernel<<<dim3(64,16), dim3(32,8)>>>(W_qkv, W_out);
    mma_gemm_kernel<0><<<dim3(12,32), 256, smem_mm>>>(x, b_qkv);
    chunk_local_kernel<<<dim3(NCH,NBH),256,smem_cl>>>(dl);
    scan_kernel<<<dim3(NBH,16),256>>>(dl);
    chunk_out_kernel<<<dim3(NCH,NBH),256,smem_co>>>(dl);
    mma_gemm_kernel<1><<<dim3(4,32), 256, smem_mm>>>(nullptr, b_out);
    ln_kernel<<<MT,128>>>(ln_g, ln_b, out);
}

// round 13
// speedup vs baseline: 1.0325x; 1.0325x over previous
#include <cuda_runtime.h>
#include <math.h>
#include <stdint.h>

#define DM 512
#define NH 8
#define ED 64
#define NB 2
#define SL 2048
#define MT (NB*SL)          // 4096 rows
#define NBH (NB*NH)         // 16 sequences
#define CK 128              // chunk length
#define NCH (SL/CK)         // 16 chunks

// ---------------- scratch (static device globals; no runtime alloc) --------
__device__ float g_q[MT*DM];
__device__ float g_k[MT*DM];
__device__ float g_v[MT*DM];
__device__ float g_attn[MT*DM];
__device__ float g_y[MT*DM];
__device__ float g_Sloc[NBH*NCH*ED*ED];
__device__ float g_Sin [NBH*NCH*ED*ED];   // row-major carry-in states [e][f]
__device__ float g_zloc[NBH*NCH*ED];
__device__ float g_zin [NBH*NCH*ED];

__device__ __forceinline__ float lam_of(const float* dl, int h){
    return 0.99f + 0.01f/(1.0f + expf(-dl[h]));
}
__device__ __forceinline__ uint32_t f2tf32(float x){
    uint32_t r; asm("cvt.rna.tf32.f32 %0, %1;" : "=r"(r) : "f"(x)); return r;
}
__device__ __forceinline__ float round_tf32(float x){
    return __uint_as_float(f2tf32(x));
}
__device__ __forceinline__ void mma_tf32(float* c, const uint4& a, const uint2& b){
    asm volatile("mma.sync.aligned.m16n8k8.row.col.f32.tf32.tf32.f32 "
        "{%0,%1,%2,%3}, {%4,%5,%6,%7}, {%8,%9}, {%0,%1,%2,%3};"
        : "+f"(c[0]), "+f"(c[1]), "+f"(c[2]), "+f"(c[3])
        : "r"(a.x), "r"(a.y), "r"(a.z), "r"(a.w), "r"(b.x), "r"(b.y));
}
// fragment-pack index helpers (m16n8k8 tf32)
__device__ __forceinline__ int Aidx(int KS, int r, int k){
    return (((r>>4)*KS + (k>>3))*32 + (r&7)*4 + (k&3))*4 + ((r>>3)&1) + 2*((k>>2)&1);
}
__device__ __forceinline__ int Bidx(int KS, int n, int k){
    return (((n>>3)*KS + (k>>3))*32 + (n&7)*4 + (k&3))*2 + ((k>>2)&1);
}

// =================== tf32 mma.sync GEMM: D = A @ W + b ======================
// A packed from row-major A (contiguous k). B packed DIRECTLY from row-major
// W[k][n] with coalesced n-loads and XOR-swizzled STS (bank-conflict-free).
// Swizzle: intra-group u32 offset ^= (gidx & 0x3C) >> 1  (bit0 stays 0).
// MODE 0: qkv = x @ W_qkv + b (epilogue: ELU maps, split q/k/v, tf32 out)
// MODE 1: y   = attn @ W_out + b (A pre-rounded)
template<int MODE>
__global__ __launch_bounds__(256) void mma_gemm_kernel(const float* __restrict__ Ain,
                                                       const float* __restrict__ W,
                                                       const float* __restrict__ bias)
{
    extern __shared__ uint32_t sm[];        // 2 bufs x (A 4096 + B 4096) u32
    constexpr int NW = (MODE==0) ? 3*DM : DM;
    const float* A = (MODE==0) ? Ain : g_attn;
    const int m0 = blockIdx.y*128, n0 = blockIdx.x*128;
    const int t = threadIdx.x, lane = t&31, wid = t>>5;
    const int wm = wid&1, wn = wid>>1;

    // A-loader constants
    const int c4    = (t&7)<<2;
    const int kkL   = c4>>3;
    const int cregL = (c4>>2)&1;
    const int rlo   = t>>3;
    const int lane0 = (rlo&7)<<2;
    const int rhi   = (t>>6)&1;
    const int mt0   = t>>7;
    const int regA  = rhi + 2*cregL;
    // B-loader constants (rows over k, contiguous n)
    const int krB   = t>>5;               // k row 0..7 (+8i)
    const int nb4   = (t&31)*4;           // n base 0..124
    const int ntB   = nb4>>3;             // n tile 0..15
    const int off0B = ((nb4&7)*4 + (krB&3))*2 + (krB>>2);

    float4 ra[4], rb[4];
    float acc[4][4][4];
    #pragma unroll
    for (int i=0;i<4;i++)
        #pragma unroll
        for (int j=0;j<4;j++)
            #pragma unroll
            for (int r=0;r<4;r++) acc[i][j][r]=0.f;

    auto ldg = [&](int c){
        const int k0 = c*32;
        #pragma unroll
        for (int i=0;i<4;i++){
            ra[i] = *(const float4*)&A[(size_t)(m0 + rlo + 32*i)*DM + k0 + c4];
            rb[i] = *(const float4*)&W[(size_t)(k0 + krB + 8*i)*NW + n0 + nb4];
        }
    };
    auto cvtA = [&](float x)->uint32_t {
        return (MODE==0) ? f2tf32(x) : __float_as_uint(x);
    };
    auto sts = [&](int buf){
        uint32_t* Ab = sm + buf*8192;
        uint32_t* Bb = Ab + 4096;
        #pragma unroll
        for (int i=0;i<4;i++){
            const int mt = mt0 + 2*i;
            const uint32_t ab = (uint32_t)(((mt*4 + kkL)*32 + lane0)*4 + regA);
            Ab[ab + 0*4] = cvtA(ra[i].x);
            Ab[ab + 1*4] = cvtA(ra[i].y);
            Ab[ab + 2*4] = cvtA(ra[i].z);
            Ab[ab + 3*4] = cvtA(ra[i].w);
            // B: k = krB + 8i -> group gidx = ntB*4 + i
            const int gidx = ntB*4 + i;
            const int s = (gidx & 0x3C) >> 1;
            uint32_t* Bg = Bb + gidx*64;
            Bg[(off0B + 0) ^ s] = f2tf32(rb[i].x);
            Bg[(off0B + 8) ^ s] = f2tf32(rb[i].y);
            Bg[(off0B +16) ^ s] = f2tf32(rb[i].z);
            Bg[(off0B +24) ^ s] = f2tf32(rb[i].w);
        }
    };
    auto compute = [&](int buf){
        const uint32_t* Ab = sm + buf*8192;
        const uint32_t* Bb = Ab + 4096;
        #pragma unroll
        for (int kk=0;kk<4;kk++){
            uint4 a[4]; uint2 b[4];
            #pragma unroll
            for (int i=0;i<4;i++)
                a[i] = *(const uint4*)&Ab[(((wm*4+i)*4+kk)*32 + lane)*4];
            #pragma unroll
            for (int j=0;j<4;j++){
                const int gidx = (wn*4+j)*4 + kk;
                const int s = (gidx & 0x3C) >> 1;
                b[j] = *(const uint2*)&Bb[gidx*64 + ((lane*2) ^ s)];
            }
            #pragma unroll
            for (int i=0;i<4;i++)
                #pragma unroll
                for (int j=0;j<4;j++)
                    mma_tf32(acc[i][j], a[i], b[j]);
        }
    };

    ldg(0); sts(0); __syncthreads();
    #pragma unroll 1
    for (int c=0;c<16;c++){
        if (c<15) ldg(c+1);
        compute(c&1);
        if (c<15) sts((c+1)&1);
        __syncthreads();
    }

    int regi = 0; float* dst;
    if (MODE==0){
        regi = n0 >> 9;
        dst = (regi==0) ? g_q : (regi==1) ? g_k : g_v;
    } else dst = g_y;
    const int nsub = (MODE==0) ? (n0 - regi*512) : n0;
    const int rowl = lane>>2, colp = (lane&3)*2;

    #pragma unroll
    for (int i=0;i<4;i++){
        #pragma unroll
        for (int j=0;j<4;j++){
            const int nn = n0   + wn*32 + j*8 + colp;
            const int nc = nsub + wn*32 + j*8 + colp;
            const float b0v = __ldg(&bias[nn]);
            const float b1v = __ldg(&bias[nn+1]);
            float v[4] = { acc[i][j][0] + b0v, acc[i][j][1] + b1v,
                           acc[i][j][2] + b0v, acc[i][j][3] + b1v };
            if (MODE==0){
                if (regi==0){
                    #pragma unroll
                    for (int e=0;e<4;e++){ float x=(v[e]>0.f)?v[e]+1.f:expf(v[e]); v[e]=round_tf32(x*0.125f); }
                } else if (regi==1){
                    #pragma unroll
                    for (int e=0;e<4;e++){ float x=(v[e]>0.f)?v[e]+1.f:expf(v[e]); v[e]=round_tf32(x); }
                } else {
                    #pragma unroll
                    for (int e=0;e<4;e++) v[e]=round_tf32(v[e]);
                }
            }
            const int r0 = m0 + wm*64 + i*16 + rowl;
            *(float2*)&dst[(size_t)r0*DM + nc]     = make_float2(v[0], v[1]);
            *(float2*)&dst[(size_t)(r0+8)*DM + nc] = make_float2(v[2], v[3]);
        }
    }
}

// ============== chunk_local via mma: S_loc = (pw*K)^T @ V,  64x64x128 =======
__global__ __launch_bounds__(256) void chunk_local_kernel(const float* __restrict__ dl)
{
    extern __shared__ uint32_t sl[];
    uint32_t* Aa = sl;            // A-pack 64x128 (KS=16) : 8192 u32
    uint32_t* Bb = sl + 8192;     // B-pack 64x128 (KS=16) : 8192 u32
    __shared__ float pw[128];
    __shared__ float zpart[4][64];

    const int c = blockIdx.x, bh = blockIdx.y;
    const int b = bh / NH, h = bh % NH;
    const int t = threadIdx.x, lane = t&31, wid = t>>5;
    const int wm = wid&1, wn = wid>>1;
    const int g = lane>>2, tg = lane&3;
    const float lam = lam_of(dl, h);
    if (t < 128) pw[t] = exp2f((float)t * log2f(lam));
    __syncthreads();

    const size_t rowbase = ((size_t)b*SL + (size_t)c*CK)*DM + h*ED;
    for (int vi = t; vi < 2048; vi += 256){
        const int j = vi >> 4, e4 = (vi & 15)*4;
        const float w = pw[127-j];
        float4 kv = *(const float4*)&g_k[rowbase + (size_t)j*DM + e4];
        Aa[Aidx(16, e4+0, j)] = f2tf32(w*kv.x);
        Aa[Aidx(16, e4+1, j)] = f2tf32(w*kv.y);
        Aa[Aidx(16, e4+2, j)] = f2tf32(w*kv.z);
        Aa[Aidx(16, e4+3, j)] = f2tf32(w*kv.w);
        float4 vv = *(const float4*)&g_v[rowbase + (size_t)j*DM + e4];
        Bb[Bidx(16, e4+0, j)] = __float_as_uint(vv.x);
        Bb[Bidx(16, e4+1, j)] = __float_as_uint(vv.y);
        Bb[Bidx(16, e4+2, j)] = __float_as_uint(vv.z);
        Bb[Bidx(16, e4+3, j)] = __float_as_uint(vv.w);
    }
    {
        const int e = t & 63, part = t >> 6;
        float z = 0.f;
        #pragma unroll 4
        for (int j = part*32; j < part*32+32; j++)
            z += pw[127-j] * g_k[rowbase + (size_t)j*DM + e];
        zpart[part][e] = z;
    }
    __syncthreads();
    if (t < ED)
        g_zloc[((size_t)bh*NCH + c)*ED + t] =
            zpart[0][t] + zpart[1][t] + zpart[2][t] + zpart[3][t];

    float acc[2][2][4];
    #pragma unroll
    for (int i=0;i<2;i++)
        #pragma unroll
        for (int j=0;j<2;j++)
            #pragma unroll
            for (int r=0;r<4;r++) acc[i][j][r]=0.f;
    #pragma unroll
    for (int kk=0;kk<16;kk++){
        uint4 a[2]; uint2 b2[2];
        #pragma unroll
        for (int i=0;i<2;i++)
            a[i] = *(const uint4*)&Aa[(((wm*2+i)*16+kk)*32 + lane)*4];
        #pragma unroll
        for (int j=0;j<2;j++)
            b2[j] = *(const uint2*)&Bb[(((wn*2+j)*16+kk)*32 + lane)*2];
        #pragma unroll
        for (int i=0;i<2;i++)
            #pragma unroll
            for (int j=0;j<2;j++)
                mma_tf32(acc[i][j], a[i], b2[j]);
    }
    const size_t sb = ((size_t)bh*NCH + c)*ED*ED;
    #pragma unroll
    for (int i=0;i<2;i++){
        #pragma unroll
        for (int j=0;j<2;j++){
            const int e0 = wm*32 + i*16 + g;
            const int f0 = wn*16 + j*8 + tg*2;
            *(float2*)&g_Sloc[sb + e0*ED + f0]     = make_float2(acc[i][j][0], acc[i][j][1]);
            *(float2*)&g_Sloc[sb + (e0+8)*ED + f0] = make_float2(acc[i][j][2], acc[i][j][3]);
        }
    }
}

// ----- PARALLEL inter-chunk scan: one thread per state element -------------
__global__ __launch_bounds__(256) void scan_kernel(const float* __restrict__ dl)
{
    const int bh  = blockIdx.x;
    const int el  = blockIdx.y*256 + threadIdx.x;    // 0..4095
    const int h   = bh % NH;
    const float lam  = lam_of(dl, h);
    const float lamC = exp2f((float)CK * log2f(lam));
    const size_t base = (size_t)bh*NCH*ED*ED + el;

    float v[NCH];
    #pragma unroll
    for (int c=0;c<NCH;c++) v[c] = g_Sloc[base + (size_t)c*ED*ED];
    float s = 0.f;
    #pragma unroll
    for (int c=0;c<NCH;c++){
        g_Sin[base + (size_t)c*ED*ED] = s;
        s = lamC*s + v[c];
    }

    if (blockIdx.y == 0 && threadIdx.x < ED){
        const size_t zb = (size_t)bh*NCH*ED + threadIdx.x;
        float zv[NCH];
        #pragma unroll
        for (int c=0;c<NCH;c++) zv[c] = g_zloc[zb + (size_t)c*ED];
        float z = 0.f;
        #pragma unroll
        for (int c=0;c<NCH;c++){
            g_zin[zb + (size_t)c*ED] = z;
            z = lamC*z + zv[c];
        }
    }
}

// ================= chunk_out: P stays in registers =========================
__global__ __launch_bounds__(256,2) void chunk_out_kernel(const float* __restrict__ dl)
{
    extern __shared__ uint32_t su[];
    uint32_t* Kb = su;            // B-pack K: n=row j (128), k=e (64), KS=8 : 8192
    uint32_t* Vb = su + 8192;     // B-pack V^T: n=f (64), k=j (128), KS=16 : 8192
    uint32_t* Sb = su + 16384;    // B-pack S^T: n=f (64), k=e (64),  KS=8  : 4096
    __shared__ float pw[132];
    __shared__ float zs[64];

    const int c = blockIdx.x, bh = blockIdx.y;
    const int b = bh / NH, h = bh % NH;
    const int t = threadIdx.x, lane = t&31, wid = t>>5;
    const int g = lane>>2, tg = lane&3;
    const float lam = lam_of(dl, h);
    if (t <= 128) pw[t] = exp2f((float)t * log2f(lam));
    if (t < ED)   zs[t] = g_zin[((size_t)bh*NCH+c)*ED + t];

    const size_t rowbase = ((size_t)b*SL + (size_t)c*CK)*DM + h*ED;
    for (int idx = t; idx < 8192; idx += 256){
        const int r = idx >> 6, k = idx & 63;
        Kb[Bidx(8, r, k)]  = __float_as_uint(g_k[rowbase + (size_t)r*DM + k]);
        Vb[Bidx(16, k, r)] = __float_as_uint(g_v[rowbase + (size_t)r*DM + k]);
    }
    {
        const size_t sbase = ((size_t)bh*NCH + c)*ED*ED;
        for (int idx = t; idx < 4096; idx += 256){
            const int e = idx >> 6, f = idx & 63;
            Sb[Bidx(8, f, e)] = f2tf32(g_Sin[sbase + idx]);
        }
    }
    __syncthreads();

    const int rb    = wid*16;
    const int ii_lo = rb + g, ii_hi = ii_lo + 8;

    uint4 qf[8];
    #pragma unroll
    for (int kk=0;kk<8;kk++){
        const float* q0 = &g_q[rowbase + (size_t)ii_lo*DM + kk*8];
        const float* q1 = &g_q[rowbase + (size_t)ii_hi*DM + kk*8];
        qf[kk].x = __float_as_uint(q0[tg]);
        qf[kk].y = __float_as_uint(q1[tg]);
        qf[kk].z = __float_as_uint(q0[tg+4]);
        qf[kk].w = __float_as_uint(q1[tg+4]);
    }

    float dq_lo = 0.f, dq_hi = 0.f;
    #pragma unroll
    for (int kk=0;kk<8;kk++){
        dq_lo += __uint_as_float(qf[kk].x)*zs[kk*8+tg]
               + __uint_as_float(qf[kk].z)*zs[kk*8+tg+4];
        dq_hi += __uint_as_float(qf[kk].y)*zs[kk*8+tg]
               + __uint_as_float(qf[kk].w)*zs[kk*8+tg+4];
    }
    dq_lo += __shfl_xor_sync(0xffffffffu, dq_lo, 1);
    dq_lo += __shfl_xor_sync(0xffffffffu, dq_lo, 2);
    dq_hi += __shfl_xor_sync(0xffffffffu, dq_hi, 1);
    dq_hi += __shfl_xor_sync(0xffffffffu, dq_hi, 2);

    float acc1[8][4];
    #pragma unroll
    for (int j=0;j<8;j++)
        #pragma unroll
        for (int r=0;r<4;r++) acc1[j][r]=0.f;
    #pragma unroll
    for (int kk=0;kk<8;kk++){
        #pragma unroll
        for (int j=0;j<8;j++){
            uint2 bb = *(const uint2*)&Sb[((j*8+kk)*32 + lane)*2];
            mma_tf32(acc1[j], qf[kk], bb);
        }
    }

    uint4 accPq[16];
    #pragma unroll
    for (int j=0;j<16;j++) accPq[j] = make_uint4(0,0,0,0);
    #pragma unroll
    for (int kk=0;kk<8;kk++){
        #pragma unroll
        for (int j=0;j<16;j++){
            uint2 bb = *(const uint2*)&Kb[((j*8+kk)*32 + lane)*2];
            mma_tf32((float*)&accPq[j], qf[kk], bb);
        }
    }

    float dens_lo = 0.f, dens_hi = 0.f;
    #pragma unroll
    for (int j=0;j<16;j++){
        const int jj0 = j*8 + 2*tg;
        const float w00 = (jj0   <= ii_lo) ? pw[ii_lo-jj0]   : 0.f;
        const float w01 = (jj0+1 <= ii_lo) ? pw[ii_lo-jj0-1] : 0.f;
        const float w10 = (jj0   <= ii_hi) ? pw[ii_hi-jj0]   : 0.f;
        const float w11 = (jj0+1 <= ii_hi) ? pw[ii_hi-jj0-1] : 0.f;
        float c0 = w00*__uint_as_float(accPq[j].x);
        float c1 = w01*__uint_as_float(accPq[j].y);
        float c2 = w10*__uint_as_float(accPq[j].z);
        float c3 = w11*__uint_as_float(accPq[j].w);
        accPq[j].x = __float_as_uint(c0);
        accPq[j].y = __float_as_uint(c1);
        accPq[j].z = __float_as_uint(c2);
        accPq[j].w = __float_as_uint(c3);
        dens_lo += c0 + c1;
        dens_hi += c2 + c3;
    }
    dens_lo += __shfl_xor_sync(0xffffffffu, dens_lo, 1);
    dens_lo += __shfl_xor_sync(0xffffffffu, dens_lo, 2);
    dens_hi += __shfl_xor_sync(0xffffffffu, dens_hi, 1);
    dens_hi += __shfl_xor_sync(0xffffffffu, dens_hi, 2);

    const int srcA = (lane & 28) | (tg>>1);
    const int srcB = srcA + 2;
    const bool odd = (tg & 1);
    #pragma unroll
    for (int j=0;j<16;j++){
        float c0 = __uint_as_float(accPq[j].x);
        float c1 = __uint_as_float(accPq[j].y);
        float c2 = __uint_as_float(accPq[j].z);
        float c3 = __uint_as_float(accPq[j].w);
        float v0a = __shfl_sync(0xffffffffu, c0, srcA);
        float v1a = __shfl_sync(0xffffffffu, c1, srcA);
        float v2a = __shfl_sync(0xffffffffu, c2, srcA);
        float v3a = __shfl_sync(0xffffffffu, c3, srcA);
        float v0b = __shfl_sync(0xffffffffu, c0, srcB);
        float v1b = __shfl_sync(0xffffffffu, c1, srcB);
        float v2b = __shfl_sync(0xffffffffu, c2, srcB);
        float v3b = __shfl_sync(0xffffffffu, c3, srcB);
        accPq[j].x = f2tf32(odd ? v1a : v0a);
        accPq[j].y = f2tf32(odd ? v3a : v2a);
        accPq[j].z = f2tf32(odd ? v1b : v0b);
        accPq[j].w = f2tf32(odd ? v3b : v2b);
    }

    float acc2[8][4];
    #pragma unroll
    for (int j=0;j<8;j++)
        #pragma unroll
        for (int r=0;r<4;r++) acc2[j][r]=0.f;
    #pragma unroll
    for (int kk=0;kk<16;kk++){
        #pragma unroll
        for (int j=0;j<8;j++){
            uint2 bb = *(const uint2*)&Vb[((j*16+kk)*32 + lane)*2];
            mma_tf32(acc2[j], accPq[kk], bb);
        }
    }

    const int mrow = b*SL + c*CK;
    const float pw_lo = pw[ii_lo+1], pw_hi = pw[ii_hi+1];
    const float inv_lo = 1.f / (pw_lo*dq_lo + dens_lo + 1e-6f);
    const float inv_hi = 1.f / (pw_hi*dq_hi + dens_hi + 1e-6f);
    #pragma unroll
    for (int j=0;j<8;j++){
        const int f0 = j*8 + 2*tg;
        const float v0 = round_tf32((pw_lo*acc1[j][0] + acc2[j][0])*inv_lo);
        const float v1 = round_tf32((pw_lo*acc1[j][1] + acc2[j][1])*inv_lo);
        const float v2 = round_tf32((pw_hi*acc1[j][2] + acc2[j][2])*inv_hi);
        const float v3 = round_tf32((pw_hi*acc1[j][3] + acc2[j][3])*inv_hi);
        *(float2*)&g_attn[(size_t)(mrow+ii_lo)*DM + h*ED + f0] = make_float2(v0, v1);
        *(float2*)&g_attn[(size_t)(mrow+ii_hi)*DM + h*ED + f0] = make_float2(v2, v3);
    }
}

// ---------------- LayerNorm ------------------------------------------------
__global__ __launch_bounds__(128) void ln_kernel(const float* __restrict__ gg,
                                                 const float* __restrict__ bb,
                                                 float* __restrict__ out)
{
    const int row = blockIdx.x, t = threadIdx.x;
    __shared__ float red[8];
    float4 v = *(const float4*)&g_y[(size_t)row*DM + t*4];
    float s  = v.x+v.y+v.z+v.w;
    float s2 = v.x*v.x+v.y*v.y+v.z*v.z+v.w*v.w;
    #pragma unroll
    for (int o=16;o;o>>=1){
        s  += __shfl_xor_sync(0xffffffffu, s,  o);
        s2 += __shfl_xor_sync(0xffffffffu, s2, o);
    }
    const int w = t>>5;
    if ((t&31)==0){ red[w]=s; red[4+w]=s2; }
    __syncthreads();
    s  = red[0]+red[1]+red[2]+red[3];
    s2 = red[4]+red[5]+red[6]+red[7];
    const float mean = s*(1.0f/DM);
    const float var  = s2*(1.0f/DM) - mean*mean;
    const float inv  = rsqrtf(var + 1e-5f);
    float4 gv = *(const float4*)&gg[t*4];
    float4 bv = *(const float4*)&bb[t*4];
    float4 o;
    o.x = (v.x-mean)*inv*gv.x + bv.x;
    o.y = (v.y-mean)*inv*gv.y + bv.y;
    o.z = (v.z-mean)*inv*gv.z + bv.z;
    o.w = (v.w-mean)*inv*gv.w + bv.w;
    *(float4*)&out[(size_t)row*DM + t*4] = o;
}

// ---------------- launch ----------------------------------------------------
extern "C" void kernel_launch(void* const* d_in, const int* in_sizes, int n_in,
                              void* d_out, int out_size)
{
    const float* x     = (const float*)d_in[0];
    const float* W_qkv = (const float*)d_in[1];
    const float* b_qkv = (const float*)d_in[2];
    const float* W_out = (const float*)d_in[3];
    const float* b_out = (const float*)d_in[4];
    const float* dl    = (const float*)d_in[5];
    const float* ln_g  = (const float*)d_in[6];
    const float* ln_b  = (const float*)d_in[7];
    float* out = (float*)d_out;

    const int smem_cl = 16384*4;                                  // 65536 B
    const int smem_co = 20480*4;                                  // 81920 B
    const int smem_mm = 2*8192*4;                                 // 65536 B
    cudaFuncSetAttribute(chunk_local_kernel,
                         cudaFuncAttributeMaxDynamicSharedMemorySize, smem_cl);
    cudaFuncSetAttribute(chunk_out_kernel,
                         cudaFuncAttributeMaxDynamicSharedMemorySize, smem_co);
    cudaFuncSetAttribute(mma_gemm_kernel<0>,
                         cudaFuncAttributeMaxDynamicSharedMemorySize, smem_mm);
    cudaFuncSetAttribute(mma_gemm_kernel<1>,
                         cudaFuncAttributeMaxDynamicSharedMemorySize, smem_mm);

    mma_gemm_kernel<0><<<dim3(12,32), 256, smem_mm>>>(x, W_qkv, b_qkv);
    chunk_local_kernel<<<dim3(NCH,NBH),256,smem_cl>>>(dl);
    scan_kernel<<<dim3(NBH,16),256>>>(dl);
    chunk_out_kernel<<<dim3(NCH,NBH),256,smem_co>>>(dl);
    mma_gemm_kernel<1><<<dim3(4,32), 256, smem_mm>>>(nullptr, W_out, b_out);
    ln_kernel<<<MT,128>>>(ln_g, ln_b, out);
}

// round 15
// speedup vs baseline: 1.1367x; 1.1010x over previous
#include <cuda_runtime.h>
#include <math.h>
#include <stdint.h>

#define DM 512
#define NH 8
#define ED 64
#define NB 2
#define SL 2048
#define MT (NB*SL)          // 4096 rows
#define NBH (NB*NH)         // 16 sequences
#define CK 128              // chunk length
#define NCH (SL/CK)         // 16 chunks

// ---------------- scratch (static device globals; no runtime alloc) --------
__device__ float g_q[MT*DM];
__device__ float g_k[MT*DM];
__device__ float g_v[MT*DM];
__device__ float g_attn[MT*DM];
__device__ float g_y[MT*DM];
__device__ float g_Sloc[NBH*NCH*ED*ED];
__device__ float g_Sin [NBH*NCH*ED*ED];   // row-major carry-in states [e][f]
__device__ float g_zloc[NBH*NCH*ED];
__device__ float g_zin [NBH*NCH*ED];

__device__ __forceinline__ float lam_of(const float* dl, int h){
    return 0.99f + 0.01f/(1.0f + expf(-dl[h]));
}
__device__ __forceinline__ uint32_t f2tf32(float x){
    uint32_t r; asm("cvt.rna.tf32.f32 %0, %1;" : "=r"(r) : "f"(x)); return r;
}
__device__ __forceinline__ float round_tf32(float x){
    return __uint_as_float(f2tf32(x));
}
__device__ __forceinline__ void mma_tf32(float* c, const uint4& a, const uint2& b){
    asm volatile("mma.sync.aligned.m16n8k8.row.col.f32.tf32.tf32.f32 "
        "{%0,%1,%2,%3}, {%4,%5,%6,%7}, {%8,%9}, {%0,%1,%2,%3};"
        : "+f"(c[0]), "+f"(c[1]), "+f"(c[2]), "+f"(c[3])
        : "r"(a.x), "r"(a.y), "r"(a.z), "r"(a.w), "r"(b.x), "r"(b.y));
}
// fragment-pack index helpers (m16n8k8 tf32)
__device__ __forceinline__ int Aidx(int KS, int r, int k){
    return (((r>>4)*KS + (k>>3))*32 + (r&7)*4 + (k&3))*4 + ((r>>3)&1) + 2*((k>>2)&1);
}
__device__ __forceinline__ int Bidx(int KS, int n, int k){
    return (((n>>3)*KS + (k>>3))*32 + (n&7)*4 + (k&3))*2 + ((k>>2)&1);
}

// =================== tf32 mma.sync GEMM: D = A @ W + b ======================
// A packed with XOR-swizzle (group ga: offset ^= (ga&7)*4) -> 2-way STS.
// B packed DIRECTLY from row-major W[k][n], XOR-swizzled (R13) -> 2-way STS.
// MODE 0: qkv = x @ W_qkv + b (epilogue: ELU maps, split q/k/v, tf32 out)
// MODE 1: y   = attn @ W_out + b (A pre-rounded)
template<int MODE>
__global__ __launch_bounds__(256) void mma_gemm_kernel(const float* __restrict__ Ain,
                                                       const float* __restrict__ W,
                                                       const float* __restrict__ bias)
{
    extern __shared__ uint32_t sm[];        // 2 bufs x (A 4096 + B 4096) u32
    constexpr int NW = (MODE==0) ? 3*DM : DM;
    const float* A = (MODE==0) ? Ain : g_attn;
    const int m0 = blockIdx.y*128, n0 = blockIdx.x*128;
    const int t = threadIdx.x, lane = t&31, wid = t>>5;
    const int wm = wid&1, wn = wid>>1;

    // A-loader constants
    const int c4    = (t&7)<<2;
    const int kkL   = c4>>3;
    const int cregL = (c4>>2)&1;
    const int rlo   = t>>3;
    const int lane0 = (rlo&7)<<2;
    const int rhi   = (t>>6)&1;
    const int mt0   = t>>7;
    const int regA  = rhi + 2*cregL;
    // B-loader constants (rows over k, contiguous n)
    const int krB   = t>>5;               // k row 0..7 (+8i)
    const int nb4   = (t&31)*4;           // n base 0..124
    const int ntB   = nb4>>3;             // n tile 0..15
    const int off0B = ((nb4&7)*4 + (krB&3))*2 + (krB>>2);

    float4 ra[4], rb[4];
    float acc[4][4][4];
    #pragma unroll
    for (int i=0;i<4;i++)
        #pragma unroll
        for (int j=0;j<4;j++)
            #pragma unroll
            for (int r=0;r<4;r++) acc[i][j][r]=0.f;

    auto ldg = [&](int c){
        const int k0 = c*32;
        #pragma unroll
        for (int i=0;i<4;i++){
            ra[i] = *(const float4*)&A[(size_t)(m0 + rlo + 32*i)*DM + k0 + c4];
            rb[i] = *(const float4*)&W[(size_t)(k0 + krB + 8*i)*NW + n0 + nb4];
        }
    };
    auto cvtA = [&](float x)->uint32_t {
        return (MODE==0) ? f2tf32(x) : __float_as_uint(x);
    };
    auto sts = [&](int buf){
        uint32_t* Ab = sm + buf*8192;
        uint32_t* Bb = Ab + 4096;
        #pragma unroll
        for (int i=0;i<4;i++){
            // A: group ga = (mt0+2i)*4 + kkL; intra-group XOR swizzle
            const int ga = (mt0 + 2*i)*4 + kkL;
            const int sA = (ga & 7)*4;
            uint32_t* Ag = Ab + ga*128;
            const int ioA = lane0*4 + regA;
            Ag[(ioA + 0*4) ^ sA] = cvtA(ra[i].x);
            Ag[(ioA + 1*4) ^ sA] = cvtA(ra[i].y);
            Ag[(ioA + 2*4) ^ sA] = cvtA(ra[i].z);
            Ag[(ioA + 3*4) ^ sA] = cvtA(ra[i].w);
            // B: group gidx = ntB*4 + i; XOR swizzle (R13)
            const int gidx = ntB*4 + i;
            const int s = (gidx & 0x3C) >> 1;
            uint32_t* Bg = Bb + gidx*64;
            Bg[(off0B + 0) ^ s] = f2tf32(rb[i].x);
            Bg[(off0B + 8) ^ s] = f2tf32(rb[i].y);
            Bg[(off0B +16) ^ s] = f2tf32(rb[i].z);
            Bg[(off0B +24) ^ s] = f2tf32(rb[i].w);
        }
    };
    auto compute = [&](int buf){
        const uint32_t* Ab = sm + buf*8192;
        const uint32_t* Bb = Ab + 4096;
        #pragma unroll
        for (int kk=0;kk<4;kk++){
            uint4 a[4]; uint2 b[4];
            #pragma unroll
            for (int i=0;i<4;i++){
                const int ga = ((wm*4+i)*4+kk);
                const int sA = (ga & 7)*4;
                a[i] = *(const uint4*)&Ab[ga*128 + ((lane*4) ^ sA)];
            }
            #pragma unroll
            for (int j=0;j<4;j++){
                const int gidx = (wn*4+j)*4 + kk;
                const int s = (gidx & 0x3C) >> 1;
                b[j] = *(const uint2*)&Bb[gidx*64 + ((lane*2) ^ s)];
            }
            #pragma unroll
            for (int i=0;i<4;i++)
                #pragma unroll
                for (int j=0;j<4;j++)
                    mma_tf32(acc[i][j], a[i], b[j]);
        }
    };

    ldg(0); sts(0); __syncthreads();
    #pragma unroll 1
    for (int c=0;c<16;c++){
        if (c<15) ldg(c+1);
        compute(c&1);
        if (c<15) sts((c+1)&1);
        __syncthreads();
    }

    int regi = 0; float* dst;
    if (MODE==0){
        regi = n0 >> 9;
        dst = (regi==0) ? g_q : (regi==1) ? g_k : g_v;
    } else dst = g_y;
    const int nsub = (MODE==0) ? (n0 - regi*512) : n0;
    const int rowl = lane>>2, colp = (lane&3)*2;

    #pragma unroll
    for (int i=0;i<4;i++){
        #pragma unroll
        for (int j=0;j<4;j++){
            const int nn = n0   + wn*32 + j*8 + colp;
            const int nc = nsub + wn*32 + j*8 + colp;
            const float b0v = __ldg(&bias[nn]);
            const float b1v = __ldg(&bias[nn+1]);
            float v[4] = { acc[i][j][0] + b0v, acc[i][j][1] + b1v,
                           acc[i][j][2] + b0v, acc[i][j][3] + b1v };
            if (MODE==0){
                if (regi==0){
                    #pragma unroll
                    for (int e=0;e<4;e++){ float x=(v[e]>0.f)?v[e]+1.f:expf(v[e]); v[e]=round_tf32(x*0.125f); }
                } else if (regi==1){
                    #pragma unroll
                    for (int e=0;e<4;e++){ float x=(v[e]>0.f)?v[e]+1.f:expf(v[e]); v[e]=round_tf32(x); }
                } else {
                    #pragma unroll
                    for (int e=0;e<4;e++) v[e]=round_tf32(v[e]);
                }
            }
            const int r0 = m0 + wm*64 + i*16 + rowl;
            *(float2*)&dst[(size_t)r0*DM + nc]     = make_float2(v[0], v[1]);
            *(float2*)&dst[(size_t)(r0+8)*DM + nc] = make_float2(v[2], v[3]);
        }
    }
}

// ============== chunk_local via mma: S_loc = (pw*K)^T @ V,  64x64x128 =======
__global__ __launch_bounds__(256) void chunk_local_kernel(const float* __restrict__ dl)
{
    extern __shared__ uint32_t sl[];
    uint32_t* Aa = sl;            // A-pack 64x128 (KS=16) : 8192 u32
    uint32_t* Bb = sl + 8192;     // B-pack 64x128 (KS=16) : 8192 u32
    __shared__ float pw[128];
    __shared__ float zpart[4][64];

    const int c = blockIdx.x, bh = blockIdx.y;
    const int b = bh / NH, h = bh % NH;
    const int t = threadIdx.x, lane = t&31, wid = t>>5;
    const int wm = wid&1, wn = wid>>1;
    const int g = lane>>2, tg = lane&3;
    const float lam = lam_of(dl, h);
    if (t < 128) pw[t] = exp2f((float)t * log2f(lam));
    __syncthreads();

    const size_t rowbase = ((size_t)b*SL + (size_t)c*CK)*DM + h*ED;
    for (int vi = t; vi < 2048; vi += 256){
        const int j = vi >> 4, e4 = (vi & 15)*4;
        const float w = pw[127-j];
        float4 kv = *(const float4*)&g_k[rowbase + (size_t)j*DM + e4];
        Aa[Aidx(16, e4+0, j)] = f2tf32(w*kv.x);
        Aa[Aidx(16, e4+1, j)] = f2tf32(w*kv.y);
        Aa[Aidx(16, e4+2, j)] = f2tf32(w*kv.z);
        Aa[Aidx(16, e4+3, j)] = f2tf32(w*kv.w);
        float4 vv = *(const float4*)&g_v[rowbase + (size_t)j*DM + e4];
        Bb[Bidx(16, e4+0, j)] = __float_as_uint(vv.x);
        Bb[Bidx(16, e4+1, j)] = __float_as_uint(vv.y);
        Bb[Bidx(16, e4+2, j)] = __float_as_uint(vv.z);
        Bb[Bidx(16, e4+3, j)] = __float_as_uint(vv.w);
    }
    {
        const int e = t & 63, part = t >> 6;
        float z = 0.f;
        #pragma unroll 4
        for (int j = part*32; j < part*32+32; j++)
            z += pw[127-j] * g_k[rowbase + (size_t)j*DM + e];
        zpart[part][e] = z;
    }
    __syncthreads();
    if (t < ED)
        g_zloc[((size_t)bh*NCH + c)*ED + t] =
            zpart[0][t] + zpart[1][t] + zpart[2][t] + zpart[3][t];

    float acc[2][2][4];
    #pragma unroll
    for (int i=0;i<2;i++)
        #pragma unroll
        for (int j=0;j<2;j++)
            #pragma unroll
            for (int r=0;r<4;r++) acc[i][j][r]=0.f;
    #pragma unroll
    for (int kk=0;kk<16;kk++){
        uint4 a[2]; uint2 b2[2];
        #pragma unroll
        for (int i=0;i<2;i++)
            a[i] = *(const uint4*)&Aa[(((wm*2+i)*16+kk)*32 + lane)*4];
        #pragma unroll
        for (int j=0;j<2;j++)
            b2[j] = *(const uint2*)&Bb[(((wn*2+j)*16+kk)*32 + lane)*2];
        #pragma unroll
        for (int i=0;i<2;i++)
            #pragma unroll
            for (int j=0;j<2;j++)
                mma_tf32(acc[i][j], a[i], b2[j]);
    }
    const size_t sb = ((size_t)bh*NCH + c)*ED*ED;
    #pragma unroll
    for (int i=0;i<2;i++){
        #pragma unroll
        for (int j=0;j<2;j++){
            const int e0 = wm*32 + i*16 + g;
            const int f0 = wn*16 + j*8 + tg*2;
            *(float2*)&g_Sloc[sb + e0*ED + f0]     = make_float2(acc[i][j][0], acc[i][j][1]);
            *(float2*)&g_Sloc[sb + (e0+8)*ED + f0] = make_float2(acc[i][j][2], acc[i][j][3]);
        }
    }
}

// ----- PARALLEL inter-chunk scan: one thread per state element -------------
__global__ __launch_bounds__(256) void scan_kernel(const float* __restrict__ dl)
{
    const int bh  = blockIdx.x;
    const int el  = blockIdx.y*256 + threadIdx.x;    // 0..4095
    const int h   = bh % NH;
    const float lam  = lam_of(dl, h);
    const float lamC = exp2f((float)CK * log2f(lam));
    const size_t base = (size_t)bh*NCH*ED*ED + el;

    float v[NCH];
    #pragma unroll
    for (int c=0;c<NCH;c++) v[c] = g_Sloc[base + (size_t)c*ED*ED];
    float s = 0.f;
    #pragma unroll
    for (int c=0;c<NCH;c++){
        g_Sin[base + (size_t)c*ED*ED] = s;
        s = lamC*s + v[c];
    }

    if (blockIdx.y == 0 && threadIdx.x < ED){
        const size_t zb = (size_t)bh*NCH*ED + threadIdx.x;
        float zv[NCH];
        #pragma unroll
        for (int c=0;c<NCH;c++) zv[c] = g_zloc[zb + (size_t)c*ED];
        float z = 0.f;
        #pragma unroll
        for (int c=0;c<NCH;c++){
            g_zin[zb + (size_t)c*ED] = z;
            z = lamC*z + zv[c];
        }
    }
}

// ================= chunk_out: P stays in registers =========================
__global__ __launch_bounds__(256,2) void chunk_out_kernel(const float* __restrict__ dl)
{
    extern __shared__ uint32_t su[];
    uint32_t* Kb = su;            // B-pack K: n=row j (128), k=e (64), KS=8 : 8192
    uint32_t* Vb = su + 8192;     // B-pack V^T: n=f (64), k=j (128), KS=16 : 8192
    uint32_t* Sb = su + 16384;    // B-pack S^T: n=f (64), k=e (64),  KS=8  : 4096
    __shared__ float pw[132];
    __shared__ float zs[64];

    const int c = blockIdx.x, bh = blockIdx.y;
    const int b = bh / NH, h = bh % NH;
    const int t = threadIdx.x, lane = t&31, wid = t>>5;
    const int g = lane>>2, tg = lane&3;
    const float lam = lam_of(dl, h);
    if (t <= 128) pw[t] = exp2f((float)t * log2f(lam));
    if (t < ED)   zs[t] = g_zin[((size_t)bh*NCH+c)*ED + t];

    const size_t rowbase = ((size_t)b*SL + (size_t)c*CK)*DM + h*ED;
    for (int idx = t; idx < 8192; idx += 256){
        const int r = idx >> 6, k = idx & 63;
        Kb[Bidx(8, r, k)]  = __float_as_uint(g_k[rowbase + (size_t)r*DM + k]);
        Vb[Bidx(16, k, r)] = __float_as_uint(g_v[rowbase + (size_t)r*DM + k]);
    }
    {
        const size_t sbase = ((size_t)bh*NCH + c)*ED*ED;
        for (int idx = t; idx < 4096; idx += 256){
            const int e = idx >> 6, f = idx & 63;
            Sb[Bidx(8, f, e)] = f2tf32(g_Sin[sbase + idx]);
        }
    }
    __syncthreads();

    const int rb    = wid*16;
    const int ii_lo = rb + g, ii_hi = ii_lo + 8;

    uint4 qf[8];
    #pragma unroll
    for (int kk=0;kk<8;kk++){
        const float* q0 = &g_q[rowbase + (size_t)ii_lo*DM + kk*8];
        const float* q1 = &g_q[rowbase + (size_t)ii_hi*DM + kk*8];
        qf[kk].x = __float_as_uint(q0[tg]);
        qf[kk].y = __float_as_uint(q1[tg]);
        qf[kk].z = __float_as_uint(q0[tg+4]);
        qf[kk].w = __float_as_uint(q1[tg+4]);
    }

    float dq_lo = 0.f, dq_hi = 0.f;
    #pragma unroll
    for (int kk=0;kk<8;kk++){
        dq_lo += __uint_as_float(qf[kk].x)*zs[kk*8+tg]
               + __uint_as_float(qf[kk].z)*zs[kk*8+tg+4];
        dq_hi += __uint_as_float(qf[kk].y)*zs[kk*8+tg]
               + __uint_as_float(qf[kk].w)*zs[kk*8+tg+4];
    }
    dq_lo += __shfl_xor_sync(0xffffffffu, dq_lo, 1);
    dq_lo += __shfl_xor_sync(0xffffffffu, dq_lo, 2);
    dq_hi += __shfl_xor_sync(0xffffffffu, dq_hi, 1);
    dq_hi += __shfl_xor_sync(0xffffffffu, dq_hi, 2);

    float acc1[8][4];
    #pragma unroll
    for (int j=0;j<8;j++)
        #pragma unroll
        for (int r=0;r<4;r++) acc1[j][r]=0.f;
    #pragma unroll
    for (int kk=0;kk<8;kk++){
        #pragma unroll
        for (int j=0;j<8;j++){
            uint2 bb = *(const uint2*)&Sb[((j*8+kk)*32 + lane)*2];
            mma_tf32(acc1[j], qf[kk], bb);
        }
    }

    uint4 accPq[16];
    #pragma unroll
    for (int j=0;j<16;j++) accPq[j] = make_uint4(0,0,0,0);
    #pragma unroll
    for (int kk=0;kk<8;kk++){
        #pragma unroll
        for (int j=0;j<16;j++){
            uint2 bb = *(const uint2*)&Kb[((j*8+kk)*32 + lane)*2];
            mma_tf32((float*)&accPq[j], qf[kk], bb);
        }
    }

    float dens_lo = 0.f, dens_hi = 0.f;
    #pragma unroll
    for (int j=0;j<16;j++){
        const int jj0 = j*8 + 2*tg;
        const float w00 = (jj0   <= ii_lo) ? pw[ii_lo-jj0]   : 0.f;
        const float w01 = (jj0+1 <= ii_lo) ? pw[ii_lo-jj0-1] : 0.f;
        const float w10 = (jj0   <= ii_hi) ? pw[ii_hi-jj0]   : 0.f;
        const float w11 = (jj0+1 <= ii_hi) ? pw[ii_hi-jj0-1] : 0.f;
        float c0 = w00*__uint_as_float(accPq[j].x);
        float c1 = w01*__uint_as_float(accPq[j].y);
        float c2 = w10*__uint_as_float(accPq[j].z);
        float c3 = w11*__uint_as_float(accPq[j].w);
        accPq[j].x = __float_as_uint(c0);
        accPq[j].y = __float_as_uint(c1);
        accPq[j].z = __float_as_uint(c2);
        accPq[j].w = __float_as_uint(c3);
        dens_lo += c0 + c1;
        dens_hi += c2 + c3;
    }
    dens_lo += __shfl_xor_sync(0xffffffffu, dens_lo, 1);
    dens_lo += __shfl_xor_sync(0xffffffffu, dens_lo, 2);
    dens_hi += __shfl_xor_sync(0xffffffffu, dens_hi, 1);
    dens_hi += __shfl_xor_sync(0xffffffffu, dens_hi, 2);

    const int srcA = (lane & 28) | (tg>>1);
    const int srcB = srcA + 2;
    const bool odd = (tg & 1);
    #pragma unroll
    for (int j=0;j<16;j++){
        float c0 = __uint_as_float(accPq[j].x);
        float c1 = __uint_as_float(accPq[j].y);
        float c2 = __uint_as_float(accPq[j].z);
        float c3 = __uint_as_float(accPq[j].w);
        float v0a = __shfl_sync(0xffffffffu, c0, srcA);
        float v1a = __shfl_sync(0xffffffffu, c1, srcA);
        float v2a = __shfl_sync(0xffffffffu, c2, srcA);
        float v3a = __shfl_sync(0xffffffffu, c3, srcA);
        float v0b = __shfl_sync(0xffffffffu, c0, srcB);
        float v1b = __shfl_sync(0xffffffffu, c1, srcB);
        float v2b = __shfl_sync(0xffffffffu, c2, srcB);
        float v3b = __shfl_sync(0xffffffffu, c3, srcB);
        accPq[j].x = f2tf32(odd ? v1a : v0a);
        accPq[j].y = f2tf32(odd ? v3a : v2a);
        accPq[j].z = f2tf32(odd ? v1b : v0b);
        accPq[j].w = f2tf32(odd ? v3b : v2b);
    }

    float acc2[8][4];
    #pragma unroll
    for (int j=0;j<8;j++)
        #pragma unroll
        for (int r=0;r<4;r++) acc2[j][r]=0.f;
    #pragma unroll
    for (int kk=0;kk<16;kk++){
        #pragma unroll
        for (int j=0;j<8;j++){
            uint2 bb = *(const uint2*)&Vb[((j*16+kk)*32 + lane)*2];
            mma_tf32(acc2[j], accPq[kk], bb);
        }
    }

    const int mrow = b*SL + c*CK;
    const float pw_lo = pw[ii_lo+1], pw_hi = pw[ii_hi+1];
    const float inv_lo = 1.f / (pw_lo*dq_lo + dens_lo + 1e-6f);
    const float inv_hi = 1.f / (pw_hi*dq_hi + dens_hi + 1e-6f);
    #pragma unroll
    for (int j=0;j<8;j++){
        const int f0 = j*8 + 2*tg;
        const float v0 = round_tf32((pw_lo*acc1[j][0] + acc2[j][0])*inv_lo);
        const float v1 = round_tf32((pw_lo*acc1[j][1] + acc2[j][1])*inv_lo);
        const float v2 = round_tf32((pw_hi*acc1[j][2] + acc2[j][2])*inv_hi);
        const float v3 = round_tf32((pw_hi*acc1[j][3] + acc2[j][3])*inv_hi);
        *(float2*)&g_attn[(size_t)(mrow+ii_lo)*DM + h*ED + f0] = make_float2(v0, v1);
        *(float2*)&g_attn[(size_t)(mrow+ii_hi)*DM + h*ED + f0] = make_float2(v2, v3);
    }
}

// ---------------- LayerNorm ------------------------------------------------
__global__ __launch_bounds__(128) void ln_kernel(const float* __restrict__ gg,
                                                 const float* __restrict__ bb,
                                                 float* __restrict__ out)
{
    const int row = blockIdx.x, t = threadIdx.x;
    __shared__ float red[8];
    float4 v = *(const float4*)&g_y[(size_t)row*DM + t*4];
    float s  = v.x+v.y+v.z+v.w;
    float s2 = v.x*v.x+v.y*v.y+v.z*v.z+v.w*v.w;
    #pragma unroll
    for (int o=16;o;o>>=1){
        s  += __shfl_xor_sync(0xffffffffu, s,  o);
        s2 += __shfl_xor_sync(0xffffffffu, s2, o);
    }
    const int w = t>>5;
    if ((t&31)==0){ red[w]=s; red[4+w]=s2; }
    __syncthreads();
    s  = red[0]+red[1]+red[2]+red[3];
    s2 = red[4]+red[5]+red[6]+red[7];
    const float mean = s*(1.0f/DM);
    const float var  = s2*(1.0f/DM) - mean*mean;
    const float inv  = rsqrtf(var + 1e-5f);
    float4 gv = *(const float4*)&gg[t*4];
    float4 bv = *(const float4*)&bb[t*4];
    float4 o;
    o.x = (v.x-mean)*inv*gv.x + bv.x;
    o.y = (v.y-mean)*inv*gv.y + bv.y;
    o.z = (v.z-mean)*inv*gv.z + bv.z;
    o.w = (v.w-mean)*inv*gv.w + bv.w;
    *(float4*)&out[(size_t)row*DM + t*4] = o;
}

// ---------------- launch ----------------------------------------------------
extern "C" void kernel_launch(void* const* d_in, const int* in_sizes, int n_in,
                              void* d_out, int out_size)
{
    const float* x     = (const float*)d_in[0];
    const float* W_qkv = (const float*)d_in[1];
    const float* b_qkv = (const float*)d_in[2];
    const float* W_out = (const float*)d_in[3];
    const float* b_out = (const float*)d_in[4];
    const float* dl    = (const float*)d_in[5];
    const float* ln_g  = (const float*)d_in[6];
    const float* ln_b  = (const float*)d_in[7];
    float* out = (float*)d_out;

    const int smem_cl = 16384*4;                                  // 65536 B
    const int smem_co = 20480*4;                                  // 81920 B
    const int smem_mm = 2*8192*4;                                 // 65536 B
    cudaFuncSetAttribute(chunk_local_kernel,
                         cudaFuncAttributeMaxDynamicSharedMemorySize, smem_cl);
    cudaFuncSetAttribute(chunk_out_kernel,
                         cudaFuncAttributeMaxDynamicSharedMemorySize, smem_co);
    cudaFuncSetAttribute(mma_gemm_kernel<0>,
                         cudaFuncAttributeMaxDynamicSharedMemorySize, smem_mm);
    cudaFuncSetAttribute(mma_gemm_kernel<1>,
                         cudaFuncAttributeMaxDynamicSharedMemorySize, smem_mm);

    mma_gemm_kernel<0><<<dim3(12,32), 256, smem_mm>>>(x, W_qkv, b_qkv);
    chunk_local_kernel<<<dim3(NCH,NBH),256,smem_cl>>>(dl);
    scan_kernel<<<dim3(NBH,16),256>>>(dl);
    chunk_out_kernel<<<dim3(NCH,NBH),256,smem_co>>>(dl);
    mma_gemm_kernel<1><<<dim3(4,32), 256, smem_mm>>>(nullptr, W_out, b_out);
    ln_kernel<<<MT,128>>>(ln_g, ln_b, out);
}

// round 16
// speedup vs baseline: 1.1370x; 1.0002x over previous
#include <cuda_runtime.h>
#include <math.h>
#include <stdint.h>

#define DM 512
#define NH 8
#define ED 64
#define NB 2
#define SL 2048
#define MT (NB*SL)          // 4096 rows
#define NBH (NB*NH)         // 16 sequences
#define CK 128              // chunk length
#define NCH (SL/CK)         // 16 chunks

// ---------------- scratch (static device globals; no runtime alloc) --------
__device__ float g_q[MT*DM];
__device__ float g_k[MT*DM];
__device__ float g_v[MT*DM];
__device__ float g_attn[MT*DM];
__device__ float g_y[MT*DM];
__device__ float g_Sloc[NBH*NCH*ED*ED];
__device__ float g_Sin [NBH*NCH*ED*ED];   // row-major carry-in states [e][f]
__device__ float g_zloc[NBH*NCH*ED];
__device__ float g_zin [NBH*NCH*ED];

__device__ __forceinline__ float lam_of(const float* dl, int h){
    return 0.99f + 0.01f/(1.0f + expf(-dl[h]));
}
__device__ __forceinline__ uint32_t f2tf32(float x){
    uint32_t r; asm("cvt.rna.tf32.f32 %0, %1;" : "=r"(r) : "f"(x)); return r;
}
__device__ __forceinline__ float round_tf32(float x){
    return __uint_as_float(f2tf32(x));
}
__device__ __forceinline__ void mma_tf32(float* c, const uint4& a, const uint2& b){
    asm volatile("mma.sync.aligned.m16n8k8.row.col.f32.tf32.tf32.f32 "
        "{%0,%1,%2,%3}, {%4,%5,%6,%7}, {%8,%9}, {%0,%1,%2,%3};"
        : "+f"(c[0]), "+f"(c[1]), "+f"(c[2]), "+f"(c[3])
        : "r"(a.x), "r"(a.y), "r"(a.z), "r"(a.w), "r"(b.x), "r"(b.y));
}
// fragment-pack index helpers (m16n8k8 tf32)
__device__ __forceinline__ int Aidx(int KS, int r, int k){
    return (((r>>4)*KS + (k>>3))*32 + (r&7)*4 + (k&3))*4 + ((r>>3)&1) + 2*((k>>2)&1);
}
__device__ __forceinline__ int Bidx(int KS, int n, int k){
    return (((n>>3)*KS + (k>>3))*32 + (n&7)*4 + (k&3))*2 + ((k>>2)&1);
}

// =================== tf32 mma.sync GEMM: D = A @ W + b ======================
// A packed with XOR-swizzle (group ga: offset ^= (ga&7)*4) -> 2-way STS.
// B packed DIRECTLY from row-major W[k][n], XOR-swizzled -> 2-way STS.
template<int MODE>
__global__ __launch_bounds__(256) void mma_gemm_kernel(const float* __restrict__ Ain,
                                                       const float* __restrict__ W,
                                                       const float* __restrict__ bias)
{
    extern __shared__ uint32_t sm[];        // 2 bufs x (A 4096 + B 4096) u32
    constexpr int NW = (MODE==0) ? 3*DM : DM;
    const float* A = (MODE==0) ? Ain : g_attn;
    const int m0 = blockIdx.y*128, n0 = blockIdx.x*128;
    const int t = threadIdx.x, lane = t&31, wid = t>>5;
    const int wm = wid&1, wn = wid>>1;

    const int c4    = (t&7)<<2;
    const int kkL   = c4>>3;
    const int cregL = (c4>>2)&1;
    const int rlo   = t>>3;
    const int lane0 = (rlo&7)<<2;
    const int rhi   = (t>>6)&1;
    const int mt0   = t>>7;
    const int regA  = rhi + 2*cregL;
    const int krB   = t>>5;
    const int nb4   = (t&31)*4;
    const int ntB   = nb4>>3;
    const int off0B = ((nb4&7)*4 + (krB&3))*2 + (krB>>2);

    float4 ra[4], rb[4];
    float acc[4][4][4];
    #pragma unroll
    for (int i=0;i<4;i++)
        #pragma unroll
        for (int j=0;j<4;j++)
            #pragma unroll
            for (int r=0;r<4;r++) acc[i][j][r]=0.f;

    auto ldg = [&](int c){
        const int k0 = c*32;
        #pragma unroll
        for (int i=0;i<4;i++){
            ra[i] = *(const float4*)&A[(size_t)(m0 + rlo + 32*i)*DM + k0 + c4];
            rb[i] = *(const float4*)&W[(size_t)(k0 + krB + 8*i)*NW + n0 + nb4];
        }
    };
    auto cvtA = [&](float x)->uint32_t {
        return (MODE==0) ? f2tf32(x) : __float_as_uint(x);
    };
    auto sts = [&](int buf){
        uint32_t* Ab = sm + buf*8192;
        uint32_t* Bb = Ab + 4096;
        #pragma unroll
        for (int i=0;i<4;i++){
            const int ga = (mt0 + 2*i)*4 + kkL;
            const int sA = (ga & 7)*4;
            uint32_t* Ag = Ab + ga*128;
            const int ioA = lane0*4 + regA;
            Ag[(ioA + 0*4) ^ sA] = cvtA(ra[i].x);
            Ag[(ioA + 1*4) ^ sA] = cvtA(ra[i].y);
            Ag[(ioA + 2*4) ^ sA] = cvtA(ra[i].z);
            Ag[(ioA + 3*4) ^ sA] = cvtA(ra[i].w);
            const int gidx = ntB*4 + i;
            const int s = (gidx & 0x3C) >> 1;
            uint32_t* Bg = Bb + gidx*64;
            Bg[(off0B + 0) ^ s] = f2tf32(rb[i].x);
            Bg[(off0B + 8) ^ s] = f2tf32(rb[i].y);
            Bg[(off0B +16) ^ s] = f2tf32(rb[i].z);
            Bg[(off0B +24) ^ s] = f2tf32(rb[i].w);
        }
    };
    auto compute = [&](int buf){
        const uint32_t* Ab = sm + buf*8192;
        const uint32_t* Bb = Ab + 4096;
        #pragma unroll
        for (int kk=0;kk<4;kk++){
            uint4 a[4]; uint2 b[4];
            #pragma unroll
            for (int i=0;i<4;i++){
                const int ga = ((wm*4+i)*4+kk);
                const int sA = (ga & 7)*4;
                a[i] = *(const uint4*)&Ab[ga*128 + ((lane*4) ^ sA)];
            }
            #pragma unroll
            for (int j=0;j<4;j++){
                const int gidx = (wn*4+j)*4 + kk;
                const int s = (gidx & 0x3C) >> 1;
                b[j] = *(const uint2*)&Bb[gidx*64 + ((lane*2) ^ s)];
            }
            #pragma unroll
            for (int i=0;i<4;i++)
                #pragma unroll
                for (int j=0;j<4;j++)
                    mma_tf32(acc[i][j], a[i], b[j]);
        }
    };

    ldg(0); sts(0); __syncthreads();
    #pragma unroll 1
    for (int c=0;c<16;c++){
        if (c<15) ldg(c+1);
        compute(c&1);
        if (c<15) sts((c+1)&1);
        __syncthreads();
    }

    int regi = 0; float* dst;
    if (MODE==0){
        regi = n0 >> 9;
        dst = (regi==0) ? g_q : (regi==1) ? g_k : g_v;
    } else dst = g_y;
    const int nsub = (MODE==0) ? (n0 - regi*512) : n0;
    const int rowl = lane>>2, colp = (lane&3)*2;

    #pragma unroll
    for (int i=0;i<4;i++){
        #pragma unroll
        for (int j=0;j<4;j++){
            const int nn = n0   + wn*32 + j*8 + colp;
            const int nc = nsub + wn*32 + j*8 + colp;
            const float b0v = __ldg(&bias[nn]);
            const float b1v = __ldg(&bias[nn+1]);
            float v[4] = { acc[i][j][0] + b0v, acc[i][j][1] + b1v,
                           acc[i][j][2] + b0v, acc[i][j][3] + b1v };
            if (MODE==0){
                if (regi==0){
                    #pragma unroll
                    for (int e=0;e<4;e++){ float x=(v[e]>0.f)?v[e]+1.f:expf(v[e]); v[e]=round_tf32(x*0.125f); }
                } else if (regi==1){
                    #pragma unroll
                    for (int e=0;e<4;e++){ float x=(v[e]>0.f)?v[e]+1.f:expf(v[e]); v[e]=round_tf32(x); }
                } else {
                    #pragma unroll
                    for (int e=0;e<4;e++) v[e]=round_tf32(v[e]);
                }
            }
            const int r0 = m0 + wm*64 + i*16 + rowl;
            *(float2*)&dst[(size_t)r0*DM + nc]     = make_float2(v[0], v[1]);
            *(float2*)&dst[(size_t)(r0+8)*DM + nc] = make_float2(v[2], v[3]);
        }
    }
}

// ============== chunk_local via mma: S_loc = (pw*K)^T @ V,  64x64x128 =======
__global__ __launch_bounds__(256) void chunk_local_kernel(const float* __restrict__ dl)
{
    extern __shared__ uint32_t sl[];
    uint32_t* Aa = sl;            // A-pack 64x128 (KS=16) : 8192 u32
    uint32_t* Bb = sl + 8192;     // B-pack 64x128 (KS=16) : 8192 u32
    __shared__ float pw[128];
    __shared__ float zpart[4][64];

    const int c = blockIdx.x, bh = blockIdx.y;
    const int b = bh / NH, h = bh % NH;
    const int t = threadIdx.x, lane = t&31, wid = t>>5;
    const int wm = wid&1, wn = wid>>1;
    const int g = lane>>2, tg = lane&3;
    const float lam = lam_of(dl, h);
    if (t < 128) pw[t] = exp2f((float)t * log2f(lam));
    __syncthreads();

    const size_t rowbase = ((size_t)b*SL + (size_t)c*CK)*DM + h*ED;
    for (int vi = t; vi < 2048; vi += 256){
        const int j = vi >> 4, e4 = (vi & 15)*4;
        const float w = pw[127-j];
        float4 kv = *(const float4*)&g_k[rowbase + (size_t)j*DM + e4];
        Aa[Aidx(16, e4+0, j)] = f2tf32(w*kv.x);
        Aa[Aidx(16, e4+1, j)] = f2tf32(w*kv.y);
        Aa[Aidx(16, e4+2, j)] = f2tf32(w*kv.z);
        Aa[Aidx(16, e4+3, j)] = f2tf32(w*kv.w);
        float4 vv = *(const float4*)&g_v[rowbase + (size_t)j*DM + e4];
        Bb[Bidx(16, e4+0, j)] = __float_as_uint(vv.x);
        Bb[Bidx(16, e4+1, j)] = __float_as_uint(vv.y);
        Bb[Bidx(16, e4+2, j)] = __float_as_uint(vv.z);
        Bb[Bidx(16, e4+3, j)] = __float_as_uint(vv.w);
    }
    {
        const int e = t & 63, part = t >> 6;
        float z = 0.f;
        #pragma unroll 4
        for (int j = part*32; j < part*32+32; j++)
            z += pw[127-j] * g_k[rowbase + (size_t)j*DM + e];
        zpart[part][e] = z;
    }
    __syncthreads();
    if (t < ED)
        g_zloc[((size_t)bh*NCH + c)*ED + t] =
            zpart[0][t] + zpart[1][t] + zpart[2][t] + zpart[3][t];

    float acc[2][2][4];
    #pragma unroll
    for (int i=0;i<2;i++)
        #pragma unroll
        for (int j=0;j<2;j++)
            #pragma unroll
            for (int r=0;r<4;r++) acc[i][j][r]=0.f;
    #pragma unroll
    for (int kk=0;kk<16;kk++){
        uint4 a[2]; uint2 b2[2];
        #pragma unroll
        for (int i=0;i<2;i++)
            a[i] = *(const uint4*)&Aa[(((wm*2+i)*16+kk)*32 + lane)*4];
        #pragma unroll
        for (int j=0;j<2;j++)
            b2[j] = *(const uint2*)&Bb[(((wn*2+j)*16+kk)*32 + lane)*2];
        #pragma unroll
        for (int i=0;i<2;i++)
            #pragma unroll
            for (int j=0;j<2;j++)
                mma_tf32(acc[i][j], a[i], b2[j]);
    }
    const size_t sb = ((size_t)bh*NCH + c)*ED*ED;
    #pragma unroll
    for (int i=0;i<2;i++){
        #pragma unroll
        for (int j=0;j<2;j++){
            const int e0 = wm*32 + i*16 + g;
            const int f0 = wn*16 + j*8 + tg*2;
            *(float2*)&g_Sloc[sb + e0*ED + f0]     = make_float2(acc[i][j][0], acc[i][j][1]);
            *(float2*)&g_Sloc[sb + (e0+8)*ED + f0] = make_float2(acc[i][j][2], acc[i][j][3]);
        }
    }
}

// ----- PARALLEL inter-chunk scan: one thread per state element -------------
__global__ __launch_bounds__(256) void scan_kernel(const float* __restrict__ dl)
{
    const int bh  = blockIdx.x;
    const int el  = blockIdx.y*256 + threadIdx.x;    // 0..4095
    const int h   = bh % NH;
    const float lam  = lam_of(dl, h);
    const float lamC = exp2f((float)CK * log2f(lam));
    const size_t base = (size_t)bh*NCH*ED*ED + el;

    float v[NCH];
    #pragma unroll
    for (int c=0;c<NCH;c++) v[c] = g_Sloc[base + (size_t)c*ED*ED];
    float s = 0.f;
    #pragma unroll
    for (int c=0;c<NCH;c++){
        g_Sin[base + (size_t)c*ED*ED] = s;
        s = lamC*s + v[c];
    }

    if (blockIdx.y == 0 && threadIdx.x < ED){
        const size_t zb = (size_t)bh*NCH*ED + threadIdx.x;
        float zv[NCH];
        #pragma unroll
        for (int c=0;c<NCH;c++) zv[c] = g_zloc[zb + (size_t)c*ED];
        float z = 0.f;
        #pragma unroll
        for (int c=0;c<NCH;c++){
            g_zin[zb + (size_t)c*ED] = z;
            z = lamC*z + zv[c];
        }
    }
}

// ================= chunk_out: P in registers + causal skipping =============
// warp wid owns rows 16*wid..16*wid+15; P column-blocks j >= jmax=2*wid+2 are
// exactly zero under the causal mask -> skip their MMAs/transform entirely.
__global__ __launch_bounds__(256,2) void chunk_out_kernel(const float* __restrict__ dl)
{
    extern __shared__ uint32_t su[];
    uint32_t* Kb = su;            // B-pack K: n=row j (128), k=e (64), KS=8 : 8192
    uint32_t* Vb = su + 8192;     // B-pack V^T: n=f (64), k=j (128), KS=16 : 8192
    uint32_t* Sb = su + 16384;    // B-pack S^T: n=f (64), k=e (64),  KS=8  : 4096
    __shared__ float pw[132];
    __shared__ float zs[64];

    const int c = blockIdx.x, bh = blockIdx.y;
    const int b = bh / NH, h = bh % NH;
    const int t = threadIdx.x, lane = t&31, wid = t>>5;
    const int g = lane>>2, tg = lane&3;
    const float lam = lam_of(dl, h);
    if (t <= 128) pw[t] = exp2f((float)t * log2f(lam));
    if (t < ED)   zs[t] = g_zin[((size_t)bh*NCH+c)*ED + t];

    const size_t rowbase = ((size_t)b*SL + (size_t)c*CK)*DM + h*ED;
    for (int idx = t; idx < 8192; idx += 256){
        const int r = idx >> 6, k = idx & 63;
        Kb[Bidx(8, r, k)]  = __float_as_uint(g_k[rowbase + (size_t)r*DM + k]);
        Vb[Bidx(16, k, r)] = __float_as_uint(g_v[rowbase + (size_t)r*DM + k]);
    }
    {
        const size_t sbase = ((size_t)bh*NCH + c)*ED*ED;
        for (int idx = t; idx < 4096; idx += 256){
            const int e = idx >> 6, f = idx & 63;
            Sb[Bidx(8, f, e)] = f2tf32(g_Sin[sbase + idx]);
        }
    }
    __syncthreads();

    const int rb    = wid*16;
    const int ii_lo = rb + g, ii_hi = ii_lo + 8;
    const int jmax  = 2*wid + 2;     // warp-uniform causal extent (j blocks)

    uint4 qf[8];
    #pragma unroll
    for (int kk=0;kk<8;kk++){
        const float* q0 = &g_q[rowbase + (size_t)ii_lo*DM + kk*8];
        const float* q1 = &g_q[rowbase + (size_t)ii_hi*DM + kk*8];
        qf[kk].x = __float_as_uint(q0[tg]);
        qf[kk].y = __float_as_uint(q1[tg]);
        qf[kk].z = __float_as_uint(q0[tg+4]);
        qf[kk].w = __float_as_uint(q1[tg+4]);
    }

    float dq_lo = 0.f, dq_hi = 0.f;
    #pragma unroll
    for (int kk=0;kk<8;kk++){
        dq_lo += __uint_as_float(qf[kk].x)*zs[kk*8+tg]
               + __uint_as_float(qf[kk].z)*zs[kk*8+tg+4];
        dq_hi += __uint_as_float(qf[kk].y)*zs[kk*8+tg]
               + __uint_as_float(qf[kk].w)*zs[kk*8+tg+4];
    }
    dq_lo += __shfl_xor_sync(0xffffffffu, dq_lo, 1);
    dq_lo += __shfl_xor_sync(0xffffffffu, dq_lo, 2);
    dq_hi += __shfl_xor_sync(0xffffffffu, dq_hi, 1);
    dq_hi += __shfl_xor_sync(0xffffffffu, dq_hi, 2);

    float acc1[8][4];
    #pragma unroll
    for (int j=0;j<8;j++)
        #pragma unroll
        for (int r=0;r<4;r++) acc1[j][r]=0.f;
    #pragma unroll
    for (int kk=0;kk<8;kk++){
        #pragma unroll
        for (int j=0;j<8;j++){
            uint2 bb = *(const uint2*)&Sb[((j*8+kk)*32 + lane)*2];
            mma_tf32(acc1[j], qf[kk], bb);
        }
    }

    // phase 1: P = Q K^T, only j < jmax (rest exactly zero under mask)
    uint4 accPq[16];
    #pragma unroll
    for (int j=0;j<16;j++) accPq[j] = make_uint4(0,0,0,0);
    #pragma unroll
    for (int j=0;j<16;j++){
        if (j < jmax){
            #pragma unroll
            for (int kk=0;kk<8;kk++){
                uint2 bb = *(const uint2*)&Kb[((j*8+kk)*32 + lane)*2];
                mma_tf32((float*)&accPq[j], qf[kk], bb);
            }
        }
    }

    // weight + mask + dens row-sums, only j < jmax
    float dens_lo = 0.f, dens_hi = 0.f;
    #pragma unroll
    for (int j=0;j<16;j++){
        if (j < jmax){
            const int jj0 = j*8 + 2*tg;
            const float w00 = (jj0   <= ii_lo) ? pw[ii_lo-jj0]   : 0.f;
            const float w01 = (jj0+1 <= ii_lo) ? pw[ii_lo-jj0-1] : 0.f;
            const float w10 = (jj0   <= ii_hi) ? pw[ii_hi-jj0]   : 0.f;
            const float w11 = (jj0+1 <= ii_hi) ? pw[ii_hi-jj0-1] : 0.f;
            float c0 = w00*__uint_as_float(accPq[j].x);
            float c1 = w01*__uint_as_float(accPq[j].y);
            float c2 = w10*__uint_as_float(accPq[j].z);
            float c3 = w11*__uint_as_float(accPq[j].w);
            accPq[j].x = __float_as_uint(c0);
            accPq[j].y = __float_as_uint(c1);
            accPq[j].z = __float_as_uint(c2);
            accPq[j].w = __float_as_uint(c3);
            dens_lo += c0 + c1;
            dens_hi += c2 + c3;
        }
    }
    dens_lo += __shfl_xor_sync(0xffffffffu, dens_lo, 1);
    dens_lo += __shfl_xor_sync(0xffffffffu, dens_lo, 2);
    dens_hi += __shfl_xor_sync(0xffffffffu, dens_hi, 1);
    dens_hi += __shfl_xor_sync(0xffffffffu, dens_hi, 2);

    // C-frag -> A-frag transform, only j < jmax
    const int srcA = (lane & 28) | (tg>>1);
    const int srcB = srcA + 2;
    const bool odd = (tg & 1);
    #pragma unroll
    for (int j=0;j<16;j++){
        if (j < jmax){
            float c0 = __uint_as_float(accPq[j].x);
            float c1 = __uint_as_float(accPq[j].y);
            float c2 = __uint_as_float(accPq[j].z);
            float c3 = __uint_as_float(accPq[j].w);
            float v0a = __shfl_sync(0xffffffffu, c0, srcA);
            float v1a = __shfl_sync(0xffffffffu, c1, srcA);
            float v2a = __shfl_sync(0xffffffffu, c2, srcA);
            float v3a = __shfl_sync(0xffffffffu, c3, srcA);
            float v0b = __shfl_sync(0xffffffffu, c0, srcB);
            float v1b = __shfl_sync(0xffffffffu, c1, srcB);
            float v2b = __shfl_sync(0xffffffffu, c2, srcB);
            float v3b = __shfl_sync(0xffffffffu, c3, srcB);
            accPq[j].x = f2tf32(odd ? v1a : v0a);
            accPq[j].y = f2tf32(odd ? v3a : v2a);
            accPq[j].z = f2tf32(odd ? v1b : v0b);
            accPq[j].w = f2tf32(odd ? v3b : v2b);
        }
    }

    // acc2 = P @ V, only kk < jmax (P blocks beyond are zero)
    float acc2[8][4];
    #pragma unroll
    for (int j=0;j<8;j++)
        #pragma unroll
        for (int r=0;r<4;r++) acc2[j][r]=0.f;
    #pragma unroll
    for (int kk=0;kk<16;kk++){
        if (kk < jmax){
            #pragma unroll
            for (int j=0;j<8;j++){
                uint2 bb = *(const uint2*)&Vb[((j*16+kk)*32 + lane)*2];
                mma_tf32(acc2[j], accPq[kk], bb);
            }
        }
    }

    const int mrow = b*SL + c*CK;
    const float pw_lo = pw[ii_lo+1], pw_hi = pw[ii_hi+1];
    const float inv_lo = 1.f / (pw_lo*dq_lo + dens_lo + 1e-6f);
    const float inv_hi = 1.f / (pw_hi*dq_hi + dens_hi + 1e-6f);
    #pragma unroll
    for (int j=0;j<8;j++){
        const int f0 = j*8 + 2*tg;
        const float v0 = round_tf32((pw_lo*acc1[j][0] + acc2[j][0])*inv_lo);
        const float v1 = round_tf32((pw_lo*acc1[j][1] + acc2[j][1])*inv_lo);
        const float v2 = round_tf32((pw_hi*acc1[j][2] + acc2[j][2])*inv_hi);
        const float v3 = round_tf32((pw_hi*acc1[j][3] + acc2[j][3])*inv_hi);
        *(float2*)&g_attn[(size_t)(mrow+ii_lo)*DM + h*ED + f0] = make_float2(v0, v1);
        *(float2*)&g_attn[(size_t)(mrow+ii_hi)*DM + h*ED + f0] = make_float2(v2, v3);
    }
}

// ---------------- LayerNorm ------------------------------------------------
__global__ __launch_bounds__(128) void ln_kernel(const float* __restrict__ gg,
                                                 const float* __restrict__ bb,
                                                 float* __restrict__ out)
{
    const int row = blockIdx.x, t = threadIdx.x;
    __shared__ float red[8];
    float4 v = *(const float4*)&g_y[(size_t)row*DM + t*4];
    float s  = v.x+v.y+v.z+v.w;
    float s2 = v.x*v.x+v.y*v.y+v.z*v.z+v.w*v.w;
    #pragma unroll
    for (int o=16;o;o>>=1){
        s  += __shfl_xor_sync(0xffffffffu, s,  o);
        s2 += __shfl_xor_sync(0xffffffffu, s2, o);
    }
    const int w = t>>5;
    if ((t&31)==0){ red[w]=s; red[4+w]=s2; }
    __syncthreads();
    s  = red[0]+red[1]+red[2]+red[3];
    s2 = red[4]+red[5]+red[6]+red[7];
    const float mean = s*(1.0f/DM);
    const float var  = s2*(1.0f/DM) - mean*mean;
    const float inv  = rsqrtf(var + 1e-5f);
    float4 gv = *(const float4*)&gg[t*4];
    float4 bv = *(const float4*)&bb[t*4];
    float4 o;
    o.x = (v.x-mean)*inv*gv.x + bv.x;
    o.y = (v.y-mean)*inv*gv.y + bv.y;
    o.z = (v.z-mean)*inv*gv.z + bv.z;
    o.w = (v.w-mean)*inv*gv.w + bv.w;
    *(float4*)&out[(size_t)row*DM + t*4] = o;
}

// ---------------- launch ----------------------------------------------------
extern "C" void kernel_launch(void* const* d_in, const int* in_sizes, int n_in,
                              void* d_out, int out_size)
{
    const float* x     = (const float*)d_in[0];
    const float* W_qkv = (const float*)d_in[1];
    const float* b_qkv = (const float*)d_in[2];
    const float* W_out = (const float*)d_in[3];
    const float* b_out = (const float*)d_in[4];
    const float* dl    = (const float*)d_in[5];
    const float* ln_g  = (const float*)d_in[6];
    const float* ln_b  = (const float*)d_in[7];
    float* out = (float*)d_out;

    const int smem_cl = 16384*4;                                  // 65536 B
    const int smem_co = 20480*4;                                  // 81920 B
    const int smem_mm = 2*8192*4;                                 // 65536 B
    cudaFuncSetAttribute(chunk_local_kernel,
                         cudaFuncAttributeMaxDynamicSharedMemorySize, smem_cl);
    cudaFuncSetAttribute(chunk_out_kernel,
                         cudaFuncAttributeMaxDynamicSharedMemorySize, smem_co);
    cudaFuncSetAttribute(mma_gemm_kernel<0>,
                         cudaFuncAttributeMaxDynamicSharedMemorySize, smem_mm);
    cudaFuncSetAttribute(mma_gemm_kernel<1>,
                         cudaFuncAttributeMaxDynamicSharedMemorySize, smem_mm);

    mma_gemm_kernel<0><<<dim3(12,32), 256, smem_mm>>>(x, W_qkv, b_qkv);
    chunk_local_kernel<<<dim3(NCH,NBH),256,smem_cl>>>(dl);
    scan_kernel<<<dim3(NBH,16),256>>>(dl);
    chunk_out_kernel<<<dim3(NCH,NBH),256,smem_co>>>(dl);
    mma_gemm_kernel<1><<<dim3(4,32), 256, smem_mm>>>(nullptr, W_out, b_out);
    ln_kernel<<<MT,128>>>(ln_g, ln_b, out);
}